// round 1
// baseline (speedup 1.0000x reference)
#include <cuda_runtime.h>

// Problem constants
#define BATCH 2
#define SEQ   2048
#define DIM   1024
#define NH    16
#define HD    64
#define M_TOT (BATCH*SEQ)   // 4096

// Scratch (no cudaMalloc allowed)
__device__ float g_q[BATCH*NH*SEQ*HD];
__device__ float g_k[BATCH*NH*SEQ*HD];
__device__ float g_v[BATCH*NH*SEQ*HD];
__device__ float g_ctx[BATCH*SEQ*DIM];

// ---------------------------------------------------------------------------
// QKV projection: C[m,n] = A[m,:] . W[:,n] + bias[n]
// A: [M_TOT, DIM] row-major (query/key/value flattened over B,S)
// W: head layout [H, DIM, HD]; column n = h*HD + e -> W[h, k, e]
// Output scattered to [B, H, S, HD]
// blockIdx.z selects q/k/v. 64x64 tile, BK=16, 256 threads, 4x4 per thread.
// ---------------------------------------------------------------------------
__global__ __launch_bounds__(256) void qkv_gemm_kernel(
    const float* __restrict__ Aq, const float* __restrict__ Ak, const float* __restrict__ Av,
    const float* __restrict__ Wq, const float* __restrict__ Wk, const float* __restrict__ Wv,
    const float* __restrict__ bq, const float* __restrict__ bk, const float* __restrict__ bv)
{
    const int which = blockIdx.z;
    const float* A    = (which == 0) ? Aq : (which == 1) ? Ak : Av;
    const float* W    = (which == 0) ? Wq : (which == 1) ? Wk : Wv;
    const float* bias = (which == 0) ? bq : (which == 1) ? bk : bv;
    float* Out        = (which == 0) ? g_q : (which == 1) ? g_k : g_v;

    __shared__ float As[16][64];
    __shared__ float Bs[16][64];

    const int m0 = blockIdx.y * 64;
    const int n0 = blockIdx.x * 64;
    const int h  = n0 >> 6;           // BN == HD == 64 -> one head per N-tile
    const int t  = threadIdx.x;
    const int tx = t & 15, ty = t >> 4;

    float c[4][4] = {};

    // A-load mapping: float4 per thread: row am (0..63), k-offset ak
    const int am = t >> 2;
    const int ak = (t & 3) * 4;
    // B-load mapping: row bkr (0..15), col be
    const int bkr = t >> 4;
    const int be  = (t & 15) * 4;

    const float* Wbase = W + (size_t)h * DIM * HD;

    for (int k0 = 0; k0 < DIM; k0 += 16) {
        float4 a4 = *(const float4*)&A[(size_t)(m0 + am) * DIM + k0 + ak];
        As[ak + 0][am] = a4.x;
        As[ak + 1][am] = a4.y;
        As[ak + 2][am] = a4.z;
        As[ak + 3][am] = a4.w;
        *(float4*)&Bs[bkr][be] = *(const float4*)&Wbase[(size_t)(k0 + bkr) * HD + be];
        __syncthreads();

        #pragma unroll
        for (int kk = 0; kk < 16; kk++) {
            float4 a = *(const float4*)&As[kk][ty * 4];
            float4 b = *(const float4*)&Bs[kk][tx * 4];
            float ar[4] = {a.x, a.y, a.z, a.w};
            float br[4] = {b.x, b.y, b.z, b.w};
            #pragma unroll
            for (int i = 0; i < 4; i++)
                #pragma unroll
                for (int j = 0; j < 4; j++)
                    c[i][j] += ar[i] * br[j];
        }
        __syncthreads();
    }

    // Epilogue: bias + scatter to [B, H, S, HD]
    #pragma unroll
    for (int i = 0; i < 4; i++) {
        const int m  = m0 + ty * 4 + i;
        const int bb = m / SEQ;
        const int s  = m % SEQ;
        float* orow = &Out[(((size_t)bb * NH + h) * SEQ + s) * HD];
        #pragma unroll
        for (int j = 0; j < 4; j++) {
            const int n = n0 + tx * 4 + j;
            orow[n & 63] = c[i][j] + bias[n];
        }
    }
}

// ---------------------------------------------------------------------------
// Output projection: out[m,n] = ctx[m,:] . Wo[:,n] + bo[n]
// Wo: [DIM, DIM] row-major
// ---------------------------------------------------------------------------
__global__ __launch_bounds__(256) void out_gemm_kernel(
    const float* __restrict__ Wo, const float* __restrict__ bo,
    float* __restrict__ out)
{
    __shared__ float As[16][64];
    __shared__ float Bs[16][64];

    const int m0 = blockIdx.y * 64;
    const int n0 = blockIdx.x * 64;
    const int t  = threadIdx.x;
    const int tx = t & 15, ty = t >> 4;

    float c[4][4] = {};

    const int am = t >> 2;
    const int ak = (t & 3) * 4;
    const int bkr = t >> 4;
    const int be  = (t & 15) * 4;

    for (int k0 = 0; k0 < DIM; k0 += 16) {
        float4 a4 = *(const float4*)&g_ctx[(size_t)(m0 + am) * DIM + k0 + ak];
        As[ak + 0][am] = a4.x;
        As[ak + 1][am] = a4.y;
        As[ak + 2][am] = a4.z;
        As[ak + 3][am] = a4.w;
        *(float4*)&Bs[bkr][be] = *(const float4*)&Wo[(size_t)(k0 + bkr) * DIM + n0 + be];
        __syncthreads();

        #pragma unroll
        for (int kk = 0; kk < 16; kk++) {
            float4 a = *(const float4*)&As[kk][ty * 4];
            float4 b = *(const float4*)&Bs[kk][tx * 4];
            float ar[4] = {a.x, a.y, a.z, a.w};
            float br[4] = {b.x, b.y, b.z, b.w};
            #pragma unroll
            for (int i = 0; i < 4; i++)
                #pragma unroll
                for (int j = 0; j < 4; j++)
                    c[i][j] += ar[i] * br[j];
        }
        __syncthreads();
    }

    #pragma unroll
    for (int i = 0; i < 4; i++) {
        const int m = m0 + ty * 4 + i;
        #pragma unroll
        for (int j = 0; j < 4; j++) {
            const int n = n0 + tx * 4 + j;
            out[(size_t)m * DIM + n] = c[i][j] + bo[n];
        }
    }
}

// ---------------------------------------------------------------------------
// Flash attention (fp32, online softmax). One thread per query row.
// Block: 128 threads = 128 query rows of one (b,h). K/V tiles 64x64 in smem.
// Writes ctx directly in concat-head [B, S, D] layout.
// ---------------------------------------------------------------------------
__global__ __launch_bounds__(128) void flash_kernel(const int* __restrict__ mask)
{
    const int bh = blockIdx.y;        // 0..B*NH-1
    const int bb = bh / NH;
    const int h  = bh % NH;
    const int t  = threadIdx.x;
    const int qi = blockIdx.x * 128 + t;

    __shared__ float Ks[64][64];
    __shared__ float Vs[64][64];
    __shared__ int   ms[64];

    // q row in registers
    const float* qptr = &g_q[((size_t)bh * SEQ + qi) * HD];
    float4 q[16];
    #pragma unroll
    for (int e = 0; e < 16; e++) q[e] = *(const float4*)&qptr[e * 4];

    float4 acc[16];
    #pragma unroll
    for (int e = 0; e < 16; e++) acc[e] = make_float4(0.f, 0.f, 0.f, 0.f);
    float m = -INFINITY, l = 0.f;
    const float scale = 0.125f;   // 1/sqrt(64)

    const float* Kbase = &g_k[(size_t)bh * SEQ * HD];
    const float* Vbase = &g_v[(size_t)bh * SEQ * HD];
    const int*   mbase = &mask[(size_t)bb * SEQ];

    for (int kv0 = 0; kv0 < SEQ; kv0 += 64) {
        // Stage 64x64 K and V tiles: 1024 float4 each / 128 threads
        #pragma unroll
        for (int i = 0; i < 8; i++) {
            const int idx = t + i * 128;
            const int r = idx >> 4;
            const int cc = (idx & 15) * 4;
            *(float4*)&Ks[r][cc] = *(const float4*)&Kbase[(size_t)(kv0 + r) * HD + cc];
            *(float4*)&Vs[r][cc] = *(const float4*)&Vbase[(size_t)(kv0 + r) * HD + cc];
        }
        if (t < 64) ms[t] = mbase[kv0 + t];
        __syncthreads();

        #pragma unroll 2
        for (int j = 0; j < 64; j++) {
            if (ms[j] == 0) continue;
            // s = q . k_j  (smem reads are warp-uniform -> broadcast)
            float sx = 0.f, sy = 0.f, sz = 0.f, sw = 0.f;
            #pragma unroll
            for (int e = 0; e < 16; e++) {
                float4 kv = *(const float4*)&Ks[j][e * 4];
                sx += q[e].x * kv.x;
                sy += q[e].y * kv.y;
                sz += q[e].z * kv.z;
                sw += q[e].w * kv.w;
            }
            float s = ((sx + sy) + (sz + sw)) * scale;

            float p;
            if (s <= m) {
                p = __expf(s - m);
                l += p;
            } else {
                // new running max: rescale (rare; ~ln(SEQ) times per row)
                const float alpha = __expf(m - s);   // exp(-inf)=0 on first hit
                l = l * alpha + 1.f;
                #pragma unroll
                for (int e = 0; e < 16; e++) {
                    acc[e].x *= alpha; acc[e].y *= alpha;
                    acc[e].z *= alpha; acc[e].w *= alpha;
                }
                m = s;
                p = 1.f;
            }
            #pragma unroll
            for (int e = 0; e < 16; e++) {
                float4 vv = *(const float4*)&Vs[j][e * 4];
                acc[e].x += p * vv.x;
                acc[e].y += p * vv.y;
                acc[e].z += p * vv.z;
                acc[e].w += p * vv.w;
            }
        }
        __syncthreads();
    }

    const float inv = (l > 0.f) ? (1.f / l) : 0.f;
    float* octx = &g_ctx[((size_t)bb * SEQ + qi) * DIM + h * HD];
    #pragma unroll
    for (int e = 0; e < 16; e++) {
        float4 o;
        o.x = acc[e].x * inv;
        o.y = acc[e].y * inv;
        o.z = acc[e].z * inv;
        o.w = acc[e].w * inv;
        *(float4*)&octx[e * 4] = o;
    }
}

// ---------------------------------------------------------------------------
extern "C" void kernel_launch(void* const* d_in, const int* in_sizes, int n_in,
                              void* d_out, int out_size)
{
    (void)in_sizes; (void)n_in; (void)out_size;
    const float* query = (const float*)d_in[0];
    const float* key   = (const float*)d_in[1];
    const float* value = (const float*)d_in[2];
    const int*   mask  = (const int*)d_in[3];
    const float* Wq = (const float*)d_in[4];
    const float* bq = (const float*)d_in[5];
    const float* Wk = (const float*)d_in[6];
    const float* bk = (const float*)d_in[7];
    const float* Wv = (const float*)d_in[8];
    const float* bv = (const float*)d_in[9];
    const float* Wo = (const float*)d_in[10];
    const float* bo = (const float*)d_in[11];
    float* out = (float*)d_out;

    dim3 gQKV(DIM / 64, M_TOT / 64, 3);
    qkv_gemm_kernel<<<gQKV, 256>>>(query, key, value, Wq, Wk, Wv, bq, bk, bv);

    dim3 gFA(SEQ / 128, BATCH * NH);
    flash_kernel<<<gFA, 128>>>(mask);

    dim3 gOUT(DIM / 64, M_TOT / 64);
    out_gemm_kernel<<<gOUT, 256>>>(Wo, bo, out);
}

// round 2
// speedup vs baseline: 1.8958x; 1.8958x over previous
#include <cuda_runtime.h>
#include <math.h>

#define BATCH 2
#define SEQ   2048
#define DIM   1024
#define NH    16
#define HD    64
#define M_TOT (BATCH*SEQ)   // 4096

// Scratch (device globals; no cudaMalloc allowed)
__device__ float g_qT[BATCH*NH*HD*SEQ];   // [bh][e][s], pre-scaled by 1/8
__device__ float g_kT[BATCH*NH*HD*SEQ];   // [bh][e][s]
__device__ float g_v [BATCH*NH*SEQ*HD];   // [bh][s][e]
__device__ float g_ctx[BATCH*SEQ*DIM];    // [b][s][h*HD+e]

// ---------------------------------------------------------------------------
// QKV projection GEMM: BM=128 (rows of A), BN=64 (= one head), BK=32.
// 128 threads, 8x8 accumulators per thread (mg = t>>3 row group, ng = t&7).
// Q and K outputs are written TRANSPOSED per head ([bh][e][s]) for flash;
// Q is additionally scaled by 1/sqrt(HD). V written natural [bh][s][e].
// ---------------------------------------------------------------------------
__global__ __launch_bounds__(128) void qkv_gemm_kernel(
    const float* __restrict__ Aq, const float* __restrict__ Ak, const float* __restrict__ Av,
    const float* __restrict__ Wq, const float* __restrict__ Wk, const float* __restrict__ Wv,
    const float* __restrict__ bq, const float* __restrict__ bk, const float* __restrict__ bv)
{
    __shared__ float As[128][33];   // pad 33: conflict-free scalar reads/writes
    __shared__ float Bs[32][64];

    const int which = blockIdx.z;
    const float* A    = (which == 0) ? Aq : (which == 1) ? Ak : Av;
    const float* W    = (which == 0) ? Wq : (which == 1) ? Wk : Wv;
    const float* bias = (which == 0) ? bq : (which == 1) ? bk : bv;

    const int h  = blockIdx.x;           // head (BN==HD==64)
    const int m0 = blockIdx.y * 128;
    const int t  = threadIdx.x;
    const int mg = t >> 3, ng = t & 7;

    const float* Wb = W + (size_t)h * DIM * HD;

    float acc[8][8] = {};

    for (int k0 = 0; k0 < DIM; k0 += 32) {
        // Stage A tile (128x32), transposed-free layout [m][k], scalar stores
        #pragma unroll
        for (int i = 0; i < 8; i++) {
            const int lin = t + i * 128;
            const int m = lin >> 3, kg = lin & 7;
            float4 a4 = *(const float4*)&A[(size_t)(m0 + m) * DIM + k0 + kg * 4];
            As[m][kg * 4 + 0] = a4.x;
            As[m][kg * 4 + 1] = a4.y;
            As[m][kg * 4 + 2] = a4.z;
            As[m][kg * 4 + 3] = a4.w;
        }
        // Stage B tile (32x64)
        #pragma unroll
        for (int i = 0; i < 4; i++) {
            const int lin = t + i * 128;
            const int kr = lin >> 4, nb = (lin & 15) * 4;
            *(float4*)&Bs[kr][nb] = *(const float4*)&Wb[(size_t)(k0 + kr) * HD + nb];
        }
        __syncthreads();

        #pragma unroll 8
        for (int kk = 0; kk < 32; kk++) {
            float a[8], b[8];
            #pragma unroll
            for (int i = 0; i < 8; i++) a[i] = As[mg * 8 + i][kk];
            float4 b0 = *(const float4*)&Bs[kk][ng * 8];
            float4 b1 = *(const float4*)&Bs[kk][ng * 8 + 4];
            b[0]=b0.x; b[1]=b0.y; b[2]=b0.z; b[3]=b0.w;
            b[4]=b1.x; b[5]=b1.y; b[6]=b1.z; b[7]=b1.w;
            #pragma unroll
            for (int i = 0; i < 8; i++)
                #pragma unroll
                for (int j = 0; j < 8; j++)
                    acc[i][j] += a[i] * b[j];
        }
        __syncthreads();
    }

    // Epilogue
    float bl[8];
    #pragma unroll
    for (int j = 0; j < 8; j++) bl[j] = bias[h * HD + ng * 8 + j];

    const int b  = m0 >> 11;              // m0 / SEQ
    const int bh = b * NH + h;
    const int sbase = (m0 & (SEQ - 1)) + mg * 8;

    if (which == 2) {
        // V natural [bh][s][e]
        #pragma unroll
        for (int i = 0; i < 8; i++) {
            float* d = &g_v[((size_t)bh * SEQ + sbase + i) * HD + ng * 8];
            float4 o0 = make_float4(acc[i][0]+bl[0], acc[i][1]+bl[1], acc[i][2]+bl[2], acc[i][3]+bl[3]);
            float4 o1 = make_float4(acc[i][4]+bl[4], acc[i][5]+bl[5], acc[i][6]+bl[6], acc[i][7]+bl[7]);
            *(float4*)&d[0] = o0;
            *(float4*)&d[4] = o1;
        }
    } else {
        float* dst = (which == 0) ? g_qT : g_kT;
        const float sc = (which == 0) ? 0.125f : 1.0f;   // 1/sqrt(64) folded into Q
        #pragma unroll
        for (int i = 0; i < 8; i++) {
            const int s = sbase + i;
            #pragma unroll
            for (int j = 0; j < 8; j++) {
                const int e = ng * 8 + j;
                dst[((size_t)bh * HD + e) * SEQ + s] = (acc[i][j] + bl[j]) * sc;
            }
        }
    }
}

// ---------------------------------------------------------------------------
// Output projection: out[m,n] = ctx[m,:] . Wo[:,n] + bo[n]; same 128x64 tiling.
// ---------------------------------------------------------------------------
__global__ __launch_bounds__(128) void out_gemm_kernel(
    const float* __restrict__ Wo, const float* __restrict__ bo,
    float* __restrict__ out)
{
    __shared__ float As[128][33];
    __shared__ float Bs[32][64];

    const int n0 = blockIdx.x * 64;
    const int m0 = blockIdx.y * 128;
    const int t  = threadIdx.x;
    const int mg = t >> 3, ng = t & 7;

    float acc[8][8] = {};

    for (int k0 = 0; k0 < DIM; k0 += 32) {
        #pragma unroll
        for (int i = 0; i < 8; i++) {
            const int lin = t + i * 128;
            const int m = lin >> 3, kg = lin & 7;
            float4 a4 = *(const float4*)&g_ctx[(size_t)(m0 + m) * DIM + k0 + kg * 4];
            As[m][kg * 4 + 0] = a4.x;
            As[m][kg * 4 + 1] = a4.y;
            As[m][kg * 4 + 2] = a4.z;
            As[m][kg * 4 + 3] = a4.w;
        }
        #pragma unroll
        for (int i = 0; i < 4; i++) {
            const int lin = t + i * 128;
            const int kr = lin >> 4, nb = (lin & 15) * 4;
            *(float4*)&Bs[kr][nb] = *(const float4*)&Wo[(size_t)(k0 + kr) * DIM + n0 + nb];
        }
        __syncthreads();

        #pragma unroll 8
        for (int kk = 0; kk < 32; kk++) {
            float a[8], b[8];
            #pragma unroll
            for (int i = 0; i < 8; i++) a[i] = As[mg * 8 + i][kk];
            float4 b0 = *(const float4*)&Bs[kk][ng * 8];
            float4 b1 = *(const float4*)&Bs[kk][ng * 8 + 4];
            b[0]=b0.x; b[1]=b0.y; b[2]=b0.z; b[3]=b0.w;
            b[4]=b1.x; b[5]=b1.y; b[6]=b1.z; b[7]=b1.w;
            #pragma unroll
            for (int i = 0; i < 8; i++)
                #pragma unroll
                for (int j = 0; j < 8; j++)
                    acc[i][j] += a[i] * b[j];
        }
        __syncthreads();
    }

    float bl[8];
    #pragma unroll
    for (int j = 0; j < 8; j++) bl[j] = bo[n0 + ng * 8 + j];

    #pragma unroll
    for (int i = 0; i < 8; i++) {
        const int m = m0 + mg * 8 + i;
        float* d = &out[(size_t)m * DIM + n0 + ng * 8];
        float4 o0 = make_float4(acc[i][0]+bl[0], acc[i][1]+bl[1], acc[i][2]+bl[2], acc[i][3]+bl[3]);
        float4 o1 = make_float4(acc[i][4]+bl[4], acc[i][5]+bl[5], acc[i][6]+bl[6], acc[i][7]+bl[7]);
        *(float4*)&d[0] = o0;
        *(float4*)&d[4] = o1;
    }
}

// ---------------------------------------------------------------------------
// Flash attention as two block GEMMs. Q-tile=128, KV-tile=64, 128 threads.
// Thread grid: qg = t>>3 (16 groups x 8 q-rows), kg = t&7 (8 groups x 8 kv / d).
// S-GEMM: s[8][8] from Qt[e][q] x Kt[e][kv] (both pre-transposed in gmem).
// Online softmax per row (shfl width 8), P written transposed+XOR-swizzled.
// PV-GEMM: ctx[8q][8d] += Pt[kv][q] x Vs[kv][d].
// ---------------------------------------------------------------------------
#define FLASH_SMEM ((64*128 + 64*64 + 64*64 + 64*128) * 4 + 64 * 4)

__global__ __launch_bounds__(128) void flash_kernel(const int* __restrict__ mask)
{
    extern __shared__ float sm[];
    float* Qt = sm;                 // [64][128]
    float* Kt = Qt + 64 * 128;      // [64][64]
    float* Vs = Kt + 64 * 64;       // [64][64]
    float* Pt = Vs + 64 * 64;       // [64][128], XOR-swizzled 16B chunks
    int*   ms = (int*)(Pt + 64 * 128);

    const int bh = blockIdx.y;
    const int b  = bh >> 4, h = bh & 15;
    const int q0 = blockIdx.x * 128;
    const int t  = threadIdx.x;
    const int qg = t >> 3, kg = t & 7;

    // Stage Q^T tile once: [e 64][q 128]
    const float* qTp = g_qT + (size_t)bh * HD * SEQ;
    #pragma unroll
    for (int i = 0; i < 16; i++) {
        const int lin = t + i * 128;
        const int e = lin >> 5, qh = (lin & 31) * 4;
        *(float4*)&Qt[e * 128 + qh] = *(const float4*)&qTp[(size_t)e * SEQ + q0 + qh];
    }

    const float* kTp = g_kT + (size_t)bh * HD * SEQ;
    const float* vp  = g_v  + (size_t)bh * SEQ * HD;
    const int*   mp  = mask + (size_t)b * SEQ;

    float ctx[8][8] = {};
    float mrow[8], lrow[8];
    #pragma unroll
    for (int i = 0; i < 8; i++) { mrow[i] = -INFINITY; lrow[i] = 0.f; }

    for (int kv0 = 0; kv0 < SEQ; kv0 += 64) {
        __syncthreads();   // protect Kt/Vs/Pt reuse (and first-iter Qt staging)

        // Stage K^T tile [e 64][kv 64] (already transposed in gmem)
        #pragma unroll
        for (int i = 0; i < 8; i++) {
            const int lin = t + i * 128;
            const int e = lin >> 4, kh = (lin & 15) * 4;
            *(float4*)&Kt[e * 64 + kh] = *(const float4*)&kTp[(size_t)e * SEQ + kv0 + kh];
        }
        // Stage V tile [kv 64][d 64] natural
        #pragma unroll
        for (int i = 0; i < 8; i++) {
            const int lin = t + i * 128;
            const int r = lin >> 4, dh = (lin & 15) * 4;
            *(float4*)&Vs[r * 64 + dh] = *(const float4*)&vp[(size_t)(kv0 + r) * HD + dh];
        }
        if (t < 64) ms[t] = mp[kv0 + t];
        __syncthreads();

        // --- S = Q . K^T (scale already folded into Q) ---
        float s[8][8] = {};
        #pragma unroll 8
        for (int kk = 0; kk < 64; kk++) {
            float4 a0 = *(const float4*)&Qt[kk * 128 + qg * 8];
            float4 a1 = *(const float4*)&Qt[kk * 128 + qg * 8 + 4];
            float4 b0 = *(const float4*)&Kt[kk * 64 + kg * 8];
            float4 b1 = *(const float4*)&Kt[kk * 64 + kg * 8 + 4];
            float a[8]  = {a0.x, a0.y, a0.z, a0.w, a1.x, a1.y, a1.z, a1.w};
            float bb[8] = {b0.x, b0.y, b0.z, b0.w, b1.x, b1.y, b1.z, b1.w};
            #pragma unroll
            for (int i = 0; i < 8; i++)
                #pragma unroll
                for (int j = 0; j < 8; j++)
                    s[i][j] += a[i] * bb[j];
        }

        // --- mask ---
        int pm[8];
        #pragma unroll
        for (int j = 0; j < 8; j++) pm[j] = ms[kg * 8 + j];
        #pragma unroll
        for (int j = 0; j < 8; j++) {
            if (!pm[j]) {
                #pragma unroll
                for (int i = 0; i < 8; i++) s[i][j] = -1e9f;
            }
        }

        // --- online softmax per row (rows spread over 8 lanes: shfl width 8) ---
        #pragma unroll
        for (int i = 0; i < 8; i++) {
            float mt = s[i][0];
            #pragma unroll
            for (int j = 1; j < 8; j++) mt = fmaxf(mt, s[i][j]);
            mt = fmaxf(mt, __shfl_xor_sync(0xffffffffu, mt, 1, 8));
            mt = fmaxf(mt, __shfl_xor_sync(0xffffffffu, mt, 2, 8));
            mt = fmaxf(mt, __shfl_xor_sync(0xffffffffu, mt, 4, 8));
            const float mnew  = fmaxf(mrow[i], mt);
            const float alpha = __expf(mrow[i] - mnew);   // 0 on first tile
            mrow[i] = mnew;
            float sum = 0.f;
            #pragma unroll
            for (int j = 0; j < 8; j++) {
                const float p = __expf(s[i][j] - mnew);
                s[i][j] = p;
                sum += p;
            }
            sum += __shfl_xor_sync(0xffffffffu, sum, 1, 8);
            sum += __shfl_xor_sync(0xffffffffu, sum, 2, 8);
            sum += __shfl_xor_sync(0xffffffffu, sum, 4, 8);
            lrow[i] = lrow[i] * alpha + sum;
            #pragma unroll
            for (int j = 0; j < 8; j++) ctx[i][j] *= alpha;
        }

        // --- write P transposed [kv][q], 16B-chunk XOR swizzle on kv>>3 ---
        #pragma unroll
        for (int j = 0; j < 8; j++) {
            const int kv = kg * 8 + j;
            float4 v0 = make_float4(s[0][j], s[1][j], s[2][j], s[3][j]);
            float4 v1 = make_float4(s[4][j], s[5][j], s[6][j], s[7][j]);
            *(float4*)&Pt[kv * 128 + (((qg * 2 + 0) ^ kg) << 2)] = v0;
            *(float4*)&Pt[kv * 128 + (((qg * 2 + 1) ^ kg) << 2)] = v1;
        }
        __syncthreads();

        // --- ctx += P . V ---
        #pragma unroll 8
        for (int kk = 0; kk < 64; kk++) {
            const int kgr = kk >> 3;
            float4 a0 = *(const float4*)&Pt[kk * 128 + (((qg * 2 + 0) ^ kgr) << 2)];
            float4 a1 = *(const float4*)&Pt[kk * 128 + (((qg * 2 + 1) ^ kgr) << 2)];
            float4 b0 = *(const float4*)&Vs[kk * 64 + kg * 8];
            float4 b1 = *(const float4*)&Vs[kk * 64 + kg * 8 + 4];
            float a[8]  = {a0.x, a0.y, a0.z, a0.w, a1.x, a1.y, a1.z, a1.w};
            float bb[8] = {b0.x, b0.y, b0.z, b0.w, b1.x, b1.y, b1.z, b1.w};
            #pragma unroll
            for (int i = 0; i < 8; i++)
                #pragma unroll
                for (int j = 0; j < 8; j++)
                    ctx[i][j] += a[i] * bb[j];
        }
    }

    // Epilogue: normalize and write concat-head ctx
    #pragma unroll
    for (int i = 0; i < 8; i++) {
        const float inv = 1.f / lrow[i];
        const int q = q0 + qg * 8 + i;
        float* d = &g_ctx[((size_t)b * SEQ + q) * DIM + h * HD + kg * 8];
        float4 o0 = make_float4(ctx[i][0]*inv, ctx[i][1]*inv, ctx[i][2]*inv, ctx[i][3]*inv);
        float4 o1 = make_float4(ctx[i][4]*inv, ctx[i][5]*inv, ctx[i][6]*inv, ctx[i][7]*inv);
        *(float4*)&d[0] = o0;
        *(float4*)&d[4] = o1;
    }
}

// ---------------------------------------------------------------------------
extern "C" void kernel_launch(void* const* d_in, const int* in_sizes, int n_in,
                              void* d_out, int out_size)
{
    (void)in_sizes; (void)n_in; (void)out_size;
    const float* query = (const float*)d_in[0];
    const float* key   = (const float*)d_in[1];
    const float* value = (const float*)d_in[2];
    const int*   mask  = (const int*)d_in[3];
    const float* Wq = (const float*)d_in[4];
    const float* bq = (const float*)d_in[5];
    const float* Wk = (const float*)d_in[6];
    const float* bk = (const float*)d_in[7];
    const float* Wv = (const float*)d_in[8];
    const float* bv = (const float*)d_in[9];
    const float* Wo = (const float*)d_in[10];
    const float* bo = (const float*)d_in[11];
    float* out = (float*)d_out;

    cudaFuncSetAttribute(flash_kernel, cudaFuncAttributeMaxDynamicSharedMemorySize, FLASH_SMEM);

    dim3 gQKV(NH, M_TOT / 128, 3);
    qkv_gemm_kernel<<<gQKV, 128>>>(query, key, value, Wq, Wk, Wv, bq, bk, bv);

    dim3 gFA(SEQ / 128, BATCH * NH);
    flash_kernel<<<gFA, 128, FLASH_SMEM>>>(mask);

    dim3 gOUT(DIM / 64, M_TOT / 128);
    out_gemm_kernel<<<gOUT, 128>>>(Wo, bo, out);
}

// round 3
// speedup vs baseline: 3.4598x; 1.8250x over previous
#include <cuda_runtime.h>
#include <math.h>
#include <stdint.h>

#define BATCH 2
#define SEQ   2048
#define DIM   1024
#define NH    16
#define HD    64
#define M_TOT (BATCH*SEQ)   // 4096

// Scratch (device globals; no cudaMalloc allowed). All natural layouts.
__device__ float g_q[(size_t)BATCH*NH*SEQ*HD];   // [bh][s][e], pre-scaled by 1/8
__device__ float g_k[(size_t)BATCH*NH*SEQ*HD];   // [bh][s][e]
__device__ float g_v[(size_t)BATCH*NH*SEQ*HD];   // [bh][s][e]
__device__ float g_ctx[(size_t)BATCH*SEQ*DIM];   // [b][s][h*HD+e]

__device__ __forceinline__ float to_tf32(float x) {
    float y;
    asm("cvt.rna.tf32.f32 %0, %1;" : "=f"(y) : "f"(x));
    return y;
}

// D += A(16x8) * B(8x8), tf32 inputs (bit patterns in .b32 regs), fp32 accum.
__device__ __forceinline__ void mma_m16n8k8(float* d, const uint32_t* a, const uint32_t* b) {
    asm volatile(
        "mma.sync.aligned.m16n8k8.row.col.f32.tf32.tf32.f32 "
        "{%0,%1,%2,%3}, {%4,%5,%6,%7}, {%8,%9}, {%0,%1,%2,%3};"
        : "+f"(d[0]), "+f"(d[1]), "+f"(d[2]), "+f"(d[3])
        : "r"(a[0]), "r"(a[1]), "r"(a[2]), "r"(a[3]), "r"(b[0]), "r"(b[1]));
}

// ---------------------------------------------------------------------------
// QKV projection on tensor cores. BM=256, BN=64(=1 head), BK=16.
// 256 threads = 8 warps, M-stacked; warp tile 32x64 (2 mfrag x 8 nfrag).
// Outputs natural [bh][s][e]; Q scaled by 1/sqrt(HD).
// ---------------------------------------------------------------------------
__global__ __launch_bounds__(256) void qkv_mma_kernel(
    const float* __restrict__ Aq, const float* __restrict__ Ak, const float* __restrict__ Av,
    const float* __restrict__ Wq, const float* __restrict__ Wk, const float* __restrict__ Wv,
    const float* __restrict__ bq, const float* __restrict__ bk, const float* __restrict__ bv)
{
    __shared__ float As[16][264];   // [k][m], stride 264 (== 8 mod 32: conflict-free frags)
    __shared__ float Bs[16][72];    // [k][n], stride 72

    const int which = blockIdx.z;
    const float* A    = (which == 0) ? Aq : (which == 1) ? Ak : Av;
    const float* W    = (which == 0) ? Wq : (which == 1) ? Wk : Wv;
    const float* bias = (which == 0) ? bq : (which == 1) ? bk : bv;
    float* Out        = (which == 0) ? g_q : (which == 1) ? g_k : g_v;
    const float sc    = (which == 0) ? 0.125f : 1.0f;

    const int h  = blockIdx.y;
    const int m0 = blockIdx.x * 256;
    const int t  = threadIdx.x;
    const int warp = t >> 5, lane = t & 31;
    const int g = lane >> 2, tg = lane & 3;
    const int wm = warp * 32;

    const float* Wb = W + (size_t)h * DIM * HD;
    const float* Arow = A + (size_t)(m0 + t) * DIM;
    const int bk_ = t >> 4, bn_ = (t & 15) * 4;

    float acc[2][8][4];
    #pragma unroll
    for (int i = 0; i < 2; i++)
        #pragma unroll
        for (int j = 0; j < 8; j++)
            #pragma unroll
            for (int c = 0; c < 4; c++) acc[i][j][c] = 0.f;

    for (int k0 = 0; k0 < DIM; k0 += 16) {
        // Stage A (thread = one m-row, 16 k values), transpose into [k][m]
        #pragma unroll
        for (int i = 0; i < 4; i++) {
            float4 v = *(const float4*)&Arow[k0 + i * 4];
            As[i*4+0][t] = to_tf32(v.x);
            As[i*4+1][t] = to_tf32(v.y);
            As[i*4+2][t] = to_tf32(v.z);
            As[i*4+3][t] = to_tf32(v.w);
        }
        // Stage B natural [k][n]
        {
            float4 w = *(const float4*)&Wb[(size_t)(k0 + bk_) * HD + bn_];
            Bs[bk_][bn_+0] = to_tf32(w.x);
            Bs[bk_][bn_+1] = to_tf32(w.y);
            Bs[bk_][bn_+2] = to_tf32(w.z);
            Bs[bk_][bn_+3] = to_tf32(w.w);
        }
        __syncthreads();

        #pragma unroll
        for (int s = 0; s < 2; s++) {
            uint32_t bf[8][2];
            #pragma unroll
            for (int nf = 0; nf < 8; nf++) {
                bf[nf][0] = __float_as_uint(Bs[s*8 + tg    ][nf*8 + g]);
                bf[nf][1] = __float_as_uint(Bs[s*8 + tg + 4][nf*8 + g]);
            }
            uint32_t af[2][4];
            #pragma unroll
            for (int mf = 0; mf < 2; mf++) {
                const int r = wm + mf * 16 + g;
                af[mf][0] = __float_as_uint(As[s*8 + tg    ][r    ]);
                af[mf][1] = __float_as_uint(As[s*8 + tg    ][r + 8]);
                af[mf][2] = __float_as_uint(As[s*8 + tg + 4][r    ]);
                af[mf][3] = __float_as_uint(As[s*8 + tg + 4][r + 8]);
            }
            #pragma unroll
            for (int mf = 0; mf < 2; mf++)
                #pragma unroll
                for (int nf = 0; nf < 8; nf++)
                    mma_m16n8k8(acc[mf][nf], af[mf], bf[nf]);
        }
        __syncthreads();
    }

    // Epilogue: bias, scale, natural [bh][s][e]
    float2 bl[8];
    #pragma unroll
    for (int nf = 0; nf < 8; nf++)
        bl[nf] = *(const float2*)&bias[h * HD + nf * 8 + 2 * tg];

    #pragma unroll
    for (int mf = 0; mf < 2; mf++) {
        #pragma unroll
        for (int half = 0; half < 2; half++) {
            const int m = m0 + wm + mf * 16 + g + half * 8;
            const int b = m >> 11, s = m & (SEQ - 1);
            float* dst = Out + (((size_t)(b * NH + h)) * SEQ + s) * HD;
            #pragma unroll
            for (int nf = 0; nf < 8; nf++) {
                float2 o;
                o.x = (acc[mf][nf][half*2+0] + bl[nf].x) * sc;
                o.y = (acc[mf][nf][half*2+1] + bl[nf].y) * sc;
                *(float2*)&dst[nf * 8 + 2 * tg] = o;
            }
        }
    }
}

// ---------------------------------------------------------------------------
// Output projection on tensor cores. Same tiling; A = g_ctx, B = Wo.
// ---------------------------------------------------------------------------
__global__ __launch_bounds__(256) void out_mma_kernel(
    const float* __restrict__ Wo, const float* __restrict__ bo,
    float* __restrict__ out)
{
    __shared__ float As[16][264];
    __shared__ float Bs[16][72];

    const int n0 = blockIdx.y * 64;
    const int m0 = blockIdx.x * 256;
    const int t  = threadIdx.x;
    const int warp = t >> 5, lane = t & 31;
    const int g = lane >> 2, tg = lane & 3;
    const int wm = warp * 32;

    const float* Arow = g_ctx + (size_t)(m0 + t) * DIM;
    const int bk_ = t >> 4, bn_ = (t & 15) * 4;

    float acc[2][8][4];
    #pragma unroll
    for (int i = 0; i < 2; i++)
        #pragma unroll
        for (int j = 0; j < 8; j++)
            #pragma unroll
            for (int c = 0; c < 4; c++) acc[i][j][c] = 0.f;

    for (int k0 = 0; k0 < DIM; k0 += 16) {
        #pragma unroll
        for (int i = 0; i < 4; i++) {
            float4 v = *(const float4*)&Arow[k0 + i * 4];
            As[i*4+0][t] = to_tf32(v.x);
            As[i*4+1][t] = to_tf32(v.y);
            As[i*4+2][t] = to_tf32(v.z);
            As[i*4+3][t] = to_tf32(v.w);
        }
        {
            float4 w = *(const float4*)&Wo[(size_t)(k0 + bk_) * DIM + n0 + bn_];
            Bs[bk_][bn_+0] = to_tf32(w.x);
            Bs[bk_][bn_+1] = to_tf32(w.y);
            Bs[bk_][bn_+2] = to_tf32(w.z);
            Bs[bk_][bn_+3] = to_tf32(w.w);
        }
        __syncthreads();

        #pragma unroll
        for (int s = 0; s < 2; s++) {
            uint32_t bf[8][2];
            #pragma unroll
            for (int nf = 0; nf < 8; nf++) {
                bf[nf][0] = __float_as_uint(Bs[s*8 + tg    ][nf*8 + g]);
                bf[nf][1] = __float_as_uint(Bs[s*8 + tg + 4][nf*8 + g]);
            }
            uint32_t af[2][4];
            #pragma unroll
            for (int mf = 0; mf < 2; mf++) {
                const int r = wm + mf * 16 + g;
                af[mf][0] = __float_as_uint(As[s*8 + tg    ][r    ]);
                af[mf][1] = __float_as_uint(As[s*8 + tg    ][r + 8]);
                af[mf][2] = __float_as_uint(As[s*8 + tg + 4][r    ]);
                af[mf][3] = __float_as_uint(As[s*8 + tg + 4][r + 8]);
            }
            #pragma unroll
            for (int mf = 0; mf < 2; mf++)
                #pragma unroll
                for (int nf = 0; nf < 8; nf++)
                    mma_m16n8k8(acc[mf][nf], af[mf], bf[nf]);
        }
        __syncthreads();
    }

    float2 bl[8];
    #pragma unroll
    for (int nf = 0; nf < 8; nf++)
        bl[nf] = *(const float2*)&bo[n0 + nf * 8 + 2 * tg];

    #pragma unroll
    for (int mf = 0; mf < 2; mf++) {
        #pragma unroll
        for (int half = 0; half < 2; half++) {
            const int m = m0 + wm + mf * 16 + g + half * 8;
            float* dst = out + (size_t)m * DIM + n0;
            #pragma unroll
            for (int nf = 0; nf < 8; nf++) {
                float2 o;
                o.x = acc[mf][nf][half*2+0] + bl[nf].x;
                o.y = acc[mf][nf][half*2+1] + bl[nf].y;
                *(float2*)&dst[nf * 8 + 2 * tg] = o;
            }
        }
    }
}

// ---------------------------------------------------------------------------
// Flash attention on tensor cores. Q-tile 128, KV-tile 64, 128 threads.
// 4 warps M-stacked; warp tile 32x64 for both S=Q.K^T and ctx+=P.V.
// smem strides 72 (== 8 mod 32) => conflict-free fragment LDS.
// ---------------------------------------------------------------------------
#define QS_OFF 0
#define KT_OFF (128*72)
#define VS_OFF (KT_OFF + 64*72)
#define PS_OFF (VS_OFF + 64*72)
#define MS_OFF (PS_OFF + 128*72)
#define FLASH_SMEM ((MS_OFF + 64) * 4)

__global__ __launch_bounds__(128) void flash_mma_kernel(const int* __restrict__ mask)
{
    extern __shared__ float sm[];
    float* Qs = sm + QS_OFF;      // [q 128][e 64] stride 72 (A natural [m][k])
    float* Kt = sm + KT_OFF;      // [e 64][kv 64] stride 72 (B as [k][n])
    float* Vs = sm + VS_OFF;      // [kv 64][d 64] stride 72 (B as [k][n])
    float* Ps = sm + PS_OFF;      // [q 128][kv 64] stride 72 (A natural [m][k])
    int*   ms = (int*)(sm + MS_OFF);

    const int bh = blockIdx.y;
    const int b  = bh >> 4, h = bh & 15;
    const int q0 = blockIdx.x * 128;
    const int t  = threadIdx.x;
    const int warp = t >> 5, lane = t & 31;
    const int g = lane >> 2, tg = lane & 3;
    const int wm = warp * 32;

    // Stage Q tile once (natural copy + tf32 cvt), float4 path
    const float* qp = g_q + ((size_t)bh * SEQ + q0) * HD;
    #pragma unroll
    for (int i = 0; i < 16; i++) {
        const int lin = t + i * 128;
        const int q = lin >> 4, c4 = (lin & 15) * 4;
        float4 v = *(const float4*)&qp[(size_t)q * HD + c4];
        float4 o = make_float4(to_tf32(v.x), to_tf32(v.y), to_tf32(v.z), to_tf32(v.w));
        *(float4*)&Qs[q * 72 + c4] = o;
    }

    const float* kp = g_k + (size_t)bh * SEQ * HD;
    const float* vp = g_v + (size_t)bh * SEQ * HD;
    const int*   mp = mask + (size_t)b * SEQ;

    float ctx[2][8][4];
    #pragma unroll
    for (int i = 0; i < 2; i++)
        #pragma unroll
        for (int j = 0; j < 8; j++)
            #pragma unroll
            for (int c = 0; c < 4; c++) ctx[i][j][c] = 0.f;
    float mrow[2][2], lrow[2][2];
    #pragma unroll
    for (int i = 0; i < 2; i++)
        #pragma unroll
        for (int j = 0; j < 2; j++) { mrow[i][j] = -INFINITY; lrow[i][j] = 0.f; }

    for (int kv0 = 0; kv0 < SEQ; kv0 += 64) {
        __syncthreads();   // protect Kt/Vs/ms reuse (also covers first-iter Qs staging)

        // Stage K transposed [e][kv] (scalar scatter, conflict-free stores)
        #pragma unroll
        for (int i = 0; i < 8; i++) {
            const int lin = t + i * 128;
            const int kv = lin & 63, e4 = lin >> 6;
            float4 v = *(const float4*)&kp[(size_t)(kv0 + kv) * HD + e4 * 4];
            Kt[(e4*4+0) * 72 + kv] = to_tf32(v.x);
            Kt[(e4*4+1) * 72 + kv] = to_tf32(v.y);
            Kt[(e4*4+2) * 72 + kv] = to_tf32(v.z);
            Kt[(e4*4+3) * 72 + kv] = to_tf32(v.w);
        }
        // Stage V natural [kv][d]
        #pragma unroll
        for (int i = 0; i < 8; i++) {
            const int lin = t + i * 128;
            const int kv = lin >> 4, c4 = (lin & 15) * 4;
            float4 v = *(const float4*)&vp[(size_t)(kv0 + kv) * HD + c4];
            float4 o = make_float4(to_tf32(v.x), to_tf32(v.y), to_tf32(v.z), to_tf32(v.w));
            *(float4*)&Vs[kv * 72 + c4] = o;
        }
        if (t < 64) ms[t] = mp[kv0 + t];
        __syncthreads();

        // --- S = Q . K^T (scale folded into Q) ---
        float sacc[2][8][4];
        #pragma unroll
        for (int i = 0; i < 2; i++)
            #pragma unroll
            for (int j = 0; j < 8; j++)
                #pragma unroll
                for (int c = 0; c < 4; c++) sacc[i][j][c] = 0.f;

        #pragma unroll
        for (int s8 = 0; s8 < 8; s8++) {
            uint32_t bf[8][2];
            #pragma unroll
            for (int nf = 0; nf < 8; nf++) {
                bf[nf][0] = __float_as_uint(Kt[(s8*8 + tg    ) * 72 + nf*8 + g]);
                bf[nf][1] = __float_as_uint(Kt[(s8*8 + tg + 4) * 72 + nf*8 + g]);
            }
            uint32_t af[2][4];
            #pragma unroll
            for (int mf = 0; mf < 2; mf++) {
                const int r = wm + mf * 16 + g;
                af[mf][0] = __float_as_uint(Qs[(r    ) * 72 + s8*8 + tg    ]);
                af[mf][1] = __float_as_uint(Qs[(r + 8) * 72 + s8*8 + tg    ]);
                af[mf][2] = __float_as_uint(Qs[(r    ) * 72 + s8*8 + tg + 4]);
                af[mf][3] = __float_as_uint(Qs[(r + 8) * 72 + s8*8 + tg + 4]);
            }
            #pragma unroll
            for (int mf = 0; mf < 2; mf++)
                #pragma unroll
                for (int nf = 0; nf < 8; nf++)
                    mma_m16n8k8(sacc[mf][nf], af[mf], bf[nf]);
        }

        // --- mask ---
        #pragma unroll
        for (int nf = 0; nf < 8; nf++) {
            const int n = nf * 8 + 2 * tg;
            const int mv0 = ms[n], mv1 = ms[n + 1];
            if (!mv0) {
                #pragma unroll
                for (int mf = 0; mf < 2; mf++) { sacc[mf][nf][0] = -1e9f; sacc[mf][nf][2] = -1e9f; }
            }
            if (!mv1) {
                #pragma unroll
                for (int mf = 0; mf < 2; mf++) { sacc[mf][nf][1] = -1e9f; sacc[mf][nf][3] = -1e9f; }
            }
        }

        // --- online softmax; rows of a frag live on 4 consecutive lanes (width-4 shfl) ---
        #pragma unroll
        for (int mf = 0; mf < 2; mf++) {
            #pragma unroll
            for (int half = 0; half < 2; half++) {
                float mloc = -INFINITY;
                #pragma unroll
                for (int nf = 0; nf < 8; nf++) {
                    mloc = fmaxf(mloc, sacc[mf][nf][half*2+0]);
                    mloc = fmaxf(mloc, sacc[mf][nf][half*2+1]);
                }
                mloc = fmaxf(mloc, __shfl_xor_sync(0xffffffffu, mloc, 1, 4));
                mloc = fmaxf(mloc, __shfl_xor_sync(0xffffffffu, mloc, 2, 4));
                const float mnew  = fmaxf(mrow[mf][half], mloc);
                const float alpha = __expf(mrow[mf][half] - mnew);   // 0 on first tile
                mrow[mf][half] = mnew;
                float sum = 0.f;
                #pragma unroll
                for (int nf = 0; nf < 8; nf++) {
                    float p0 = __expf(sacc[mf][nf][half*2+0] - mnew);
                    float p1 = __expf(sacc[mf][nf][half*2+1] - mnew);
                    sacc[mf][nf][half*2+0] = p0;
                    sacc[mf][nf][half*2+1] = p1;
                    sum += p0 + p1;
                }
                sum += __shfl_xor_sync(0xffffffffu, sum, 1, 4);
                sum += __shfl_xor_sync(0xffffffffu, sum, 2, 4);
                lrow[mf][half] = lrow[mf][half] * alpha + sum;
                #pragma unroll
                for (int nf = 0; nf < 8; nf++) {
                    ctx[mf][nf][half*2+0] *= alpha;
                    ctx[mf][nf][half*2+1] *= alpha;
                }
            }
        }

        // --- write P to smem [q][kv] (warp-private rows; float2 stores) ---
        #pragma unroll
        for (int mf = 0; mf < 2; mf++) {
            #pragma unroll
            for (int half = 0; half < 2; half++) {
                const int r = wm + mf * 16 + g + half * 8;
                #pragma unroll
                for (int nf = 0; nf < 8; nf++) {
                    float2 o;
                    o.x = to_tf32(sacc[mf][nf][half*2+0]);
                    o.y = to_tf32(sacc[mf][nf][half*2+1]);
                    *(float2*)&Ps[r * 72 + nf * 8 + 2 * tg] = o;
                }
            }
        }
        __syncwarp();

        // --- ctx += P . V ---
        #pragma unroll
        for (int s8 = 0; s8 < 8; s8++) {
            uint32_t bf[8][2];
            #pragma unroll
            for (int nf = 0; nf < 8; nf++) {
                bf[nf][0] = __float_as_uint(Vs[(s8*8 + tg    ) * 72 + nf*8 + g]);
                bf[nf][1] = __float_as_uint(Vs[(s8*8 + tg + 4) * 72 + nf*8 + g]);
            }
            uint32_t af[2][4];
            #pragma unroll
            for (int mf = 0; mf < 2; mf++) {
                const int r = wm + mf * 16 + g;
                af[mf][0] = __float_as_uint(Ps[(r    ) * 72 + s8*8 + tg    ]);
                af[mf][1] = __float_as_uint(Ps[(r + 8) * 72 + s8*8 + tg    ]);
                af[mf][2] = __float_as_uint(Ps[(r    ) * 72 + s8*8 + tg + 4]);
                af[mf][3] = __float_as_uint(Ps[(r + 8) * 72 + s8*8 + tg + 4]);
            }
            #pragma unroll
            for (int mf = 0; mf < 2; mf++)
                #pragma unroll
                for (int nf = 0; nf < 8; nf++)
                    mma_m16n8k8(ctx[mf][nf], af[mf], bf[nf]);
        }
    }

    // Epilogue: normalize + concat-head write
    #pragma unroll
    for (int mf = 0; mf < 2; mf++) {
        #pragma unroll
        for (int half = 0; half < 2; half++) {
            const float inv = 1.f / lrow[mf][half];
            const int q = q0 + wm + mf * 16 + g + half * 8;
            float* dst = &g_ctx[((size_t)b * SEQ + q) * DIM + h * HD];
            #pragma unroll
            for (int nf = 0; nf < 8; nf++) {
                float2 o;
                o.x = ctx[mf][nf][half*2+0] * inv;
                o.y = ctx[mf][nf][half*2+1] * inv;
                *(float2*)&dst[nf * 8 + 2 * tg] = o;
            }
        }
    }
}

// ---------------------------------------------------------------------------
extern "C" void kernel_launch(void* const* d_in, const int* in_sizes, int n_in,
                              void* d_out, int out_size)
{
    (void)in_sizes; (void)n_in; (void)out_size;
    const float* query = (const float*)d_in[0];
    const float* key   = (const float*)d_in[1];
    const float* value = (const float*)d_in[2];
    const int*   mask  = (const int*)d_in[3];
    const float* Wq = (const float*)d_in[4];
    const float* bq = (const float*)d_in[5];
    const float* Wk = (const float*)d_in[6];
    const float* bk = (const float*)d_in[7];
    const float* Wv = (const float*)d_in[8];
    const float* bv = (const float*)d_in[9];
    const float* Wo = (const float*)d_in[10];
    const float* bo = (const float*)d_in[11];
    float* out = (float*)d_out;

    cudaFuncSetAttribute(flash_mma_kernel, cudaFuncAttributeMaxDynamicSharedMemorySize, FLASH_SMEM);

    dim3 gQKV(M_TOT / 256, NH, 3);
    qkv_mma_kernel<<<gQKV, 256>>>(query, key, value, Wq, Wk, Wv, bq, bk, bv);

    dim3 gFA(SEQ / 128, BATCH * NH);
    flash_mma_kernel<<<gFA, 128, FLASH_SMEM>>>(mask);

    dim3 gOUT(M_TOT / 256, DIM / 64);
    out_mma_kernel<<<gOUT, 256>>>(Wo, bo, out);
}

// round 4
// speedup vs baseline: 4.9624x; 1.4343x over previous
#include <cuda_runtime.h>
#include <math.h>
#include <stdint.h>

#define BATCH 2
#define SEQ   2048
#define DIM   1024
#define NH    16
#define HD    64
#define M_TOT (BATCH*SEQ)           // 4096
#define SCALE_Q 0.18033688011112042f  // 0.125 * log2(e): scores land in log2 domain

// ---- scratch (device globals; no cudaMalloc allowed) ----
__device__ float g_aq[(size_t)M_TOT*DIM];      // tf32-rounded activations
__device__ float g_ak[(size_t)M_TOT*DIM];
__device__ float g_av[(size_t)M_TOT*DIM];
__device__ float g_wq[(size_t)NH*DIM*HD];      // tf32-rounded weights
__device__ float g_wk[(size_t)NH*DIM*HD];
__device__ float g_wv[(size_t)NH*DIM*HD];
__device__ float g_wo[(size_t)DIM*DIM];
__device__ float g_q [(size_t)BATCH*NH*SEQ*HD]; // [bh][s][e], pre-scaled by 0.125*log2e, tf32
__device__ float g_kT[(size_t)BATCH*NH*HD*SEQ]; // [bh][e][s], tf32
__device__ float g_v [(size_t)BATCH*NH*SEQ*HD]; // [bh][s][e], tf32
__device__ float g_ctx[(size_t)M_TOT*DIM];      // [b][s][h*HD+e], tf32

// ---- helpers ----
__device__ __forceinline__ float to_tf32(float x) {
    float y; asm("cvt.rna.tf32.f32 %0, %1;" : "=f"(y) : "f"(x)); return y;
}
__device__ __forceinline__ float ex2f(float x) {
    float y; asm("ex2.approx.f32 %0, %1;" : "=f"(y) : "f"(x)); return y;
}
__device__ __forceinline__ uint32_t smem_u32(const void* p) {
    return (uint32_t)__cvta_generic_to_shared(p);
}
#define CP_ASYNC16(dst, src) \
    asm volatile("cp.async.cg.shared.global [%0], [%1], 16;" :: "r"(dst), "l"(src))
#define CP_COMMIT() asm volatile("cp.async.commit_group;")
#define CP_WAIT0()  asm volatile("cp.async.wait_group 0;")

// D += A(16x8) * B(8x8), tf32 inputs, fp32 accum.
__device__ __forceinline__ void mma_m16n8k8(float* d, const uint32_t* a, const uint32_t* b) {
    asm volatile(
        "mma.sync.aligned.m16n8k8.row.col.f32.tf32.tf32.f32 "
        "{%0,%1,%2,%3}, {%4,%5,%6,%7}, {%8,%9}, {%0,%1,%2,%3};"
        : "+f"(d[0]), "+f"(d[1]), "+f"(d[2]), "+f"(d[3])
        : "r"(a[0]), "r"(a[1]), "r"(a[2]), "r"(a[3]), "r"(b[0]), "r"(b[1]));
}

// ---------------------------------------------------------------------------
// Prep: tf32-round inputs so mainloops can cp.async raw bits.
// ---------------------------------------------------------------------------
__global__ __launch_bounds__(256) void prep_act_kernel(
    const float* __restrict__ q, const float* __restrict__ k, const float* __restrict__ v)
{
    const int z = blockIdx.y;
    const float4* s = (const float4*)(z == 0 ? q : z == 1 ? k : v);
    float4* d = (float4*)(z == 0 ? g_aq : z == 1 ? g_ak : g_av);
    const size_t i = (size_t)blockIdx.x * 256 + threadIdx.x;   // 1,048,576 float4
    float4 x = s[i];
    d[i] = make_float4(to_tf32(x.x), to_tf32(x.y), to_tf32(x.z), to_tf32(x.w));
}
__global__ __launch_bounds__(256) void prep_w_kernel(
    const float* __restrict__ wq, const float* __restrict__ wk,
    const float* __restrict__ wv, const float* __restrict__ wo)
{
    const int z = blockIdx.y;
    const float4* s = (const float4*)(z == 0 ? wq : z == 1 ? wk : z == 2 ? wv : wo);
    float4* d = (float4*)(z == 0 ? g_wq : z == 1 ? g_wk : z == 2 ? g_wv : g_wo);
    const size_t i = (size_t)blockIdx.x * 256 + threadIdx.x;   // 262,144 float4
    float4 x = s[i];
    d[i] = make_float4(to_tf32(x.x), to_tf32(x.y), to_tf32(x.z), to_tf32(x.w));
}

// ---------------------------------------------------------------------------
// GEMM template constants: BM=256, BN=128, BK=32, 512 threads (16 warps 8x2).
// As [m][k] stride 36 (4 mod 32 -> conflict-free A-frags); Bs [k][n] stride 136.
// ---------------------------------------------------------------------------
#define GA_STRIDE 36
#define GB_STRIDE 136
#define G_STAGE   (256*GA_STRIDE + 32*GB_STRIDE)   // 13568 floats
#define GEMM_SMEM (2*G_STAGE*4)                    // 108,544 B

// QKV projection: A[m,1024] x W_head2[k][n(128=2 heads)] -> q/kT/v (tf32-rounded)
__global__ __launch_bounds__(512) void qkv_mma_kernel(
    const float* __restrict__ bq, const float* __restrict__ bk, const float* __restrict__ bv)
{
    extern __shared__ float sm[];
    const int which = blockIdx.z;
    const float* A    = which == 0 ? g_aq : which == 1 ? g_ak : g_av;
    const float* W    = which == 0 ? g_wq : which == 1 ? g_wk : g_wv;
    const float* bias = which == 0 ? bq   : which == 1 ? bk   : bv;

    const int m0 = blockIdx.x * 256;
    const int hp = blockIdx.y;                 // head pair: heads 2hp, 2hp+1
    const int t = threadIdx.x;
    const int warp = t >> 5, lane = t & 31, g = lane >> 2, tg = lane & 3;
    const int wm = (warp >> 1) * 32, wn = (warp & 1) * 64;

    const float* Wb = W + (size_t)(hp * 2) * DIM * HD;

    auto issue = [&](int k0, int st) {
        float* As = sm + st * G_STAGE;
        float* Bs = As + 256 * GA_STRIDE;
        #pragma unroll
        for (int j = 0; j < 4; j++) {
            const int lin = j * 512 + t;
            const int r = lin >> 3, c = (lin & 7) * 4;
            CP_ASYNC16(smem_u32(&As[r * GA_STRIDE + c]),
                       &A[(size_t)(m0 + r) * DIM + k0 + c]);
        }
        #pragma unroll
        for (int j = 0; j < 2; j++) {
            const int lin = j * 512 + t;
            const int r = lin >> 5, n = (lin & 31) * 4;
            CP_ASYNC16(smem_u32(&Bs[r * GB_STRIDE + n]),
                       &Wb[(size_t)(n >> 6) * DIM * HD + (size_t)(k0 + r) * HD + (n & 63)]);
        }
    };

    float acc[2][8][4];
    #pragma unroll
    for (int i = 0; i < 2; i++)
        #pragma unroll
        for (int j = 0; j < 8; j++)
            #pragma unroll
            for (int c = 0; c < 4; c++) acc[i][j][c] = 0.f;

    issue(0, 0); CP_COMMIT();
    for (int it = 0; it < 32; it++) {
        CP_WAIT0(); __syncthreads();
        if (it < 31) { issue((it + 1) * 32, (it + 1) & 1); CP_COMMIT(); }
        const float* As = sm + (it & 1) * G_STAGE;
        const float* Bs = As + 256 * GA_STRIDE;
        #pragma unroll
        for (int s8 = 0; s8 < 4; s8++) {
            const int k = s8 * 8;
            uint32_t bf[8][2];
            #pragma unroll
            for (int nf = 0; nf < 8; nf++) {
                bf[nf][0] = __float_as_uint(Bs[(k + tg    ) * GB_STRIDE + wn + nf * 8 + g]);
                bf[nf][1] = __float_as_uint(Bs[(k + tg + 4) * GB_STRIDE + wn + nf * 8 + g]);
            }
            uint32_t af[2][4];
            #pragma unroll
            for (int mf = 0; mf < 2; mf++) {
                const int r = wm + mf * 16 + g;
                af[mf][0] = __float_as_uint(As[(r    ) * GA_STRIDE + k + tg    ]);
                af[mf][1] = __float_as_uint(As[(r + 8) * GA_STRIDE + k + tg    ]);
                af[mf][2] = __float_as_uint(As[(r    ) * GA_STRIDE + k + tg + 4]);
                af[mf][3] = __float_as_uint(As[(r + 8) * GA_STRIDE + k + tg + 4]);
            }
            #pragma unroll
            for (int mf = 0; mf < 2; mf++)
                #pragma unroll
                for (int nf = 0; nf < 8; nf++)
                    mma_m16n8k8(acc[mf][nf], af[mf], bf[nf]);
        }
    }

    // epilogue: head is uniform per warp (wn selects it)
    const int h = hp * 2 + (wn >> 6);
    float2 bl[8];
    #pragma unroll
    for (int nf = 0; nf < 8; nf++)
        bl[nf] = *(const float2*)&bias[h * HD + nf * 8 + 2 * tg];

    #pragma unroll
    for (int mf = 0; mf < 2; mf++) {
        #pragma unroll
        for (int half = 0; half < 2; half++) {
            const int m = m0 + wm + mf * 16 + g + half * 8;
            const int b = m >> 11, s = m & (SEQ - 1);
            const int bh = b * NH + h;
            if (which == 0) {
                float* dst = g_q + ((size_t)bh * SEQ + s) * HD;
                #pragma unroll
                for (int nf = 0; nf < 8; nf++) {
                    float2 o;
                    o.x = to_tf32((acc[mf][nf][half*2+0] + bl[nf].x) * SCALE_Q);
                    o.y = to_tf32((acc[mf][nf][half*2+1] + bl[nf].y) * SCALE_Q);
                    *(float2*)&dst[nf * 8 + 2 * tg] = o;
                }
            } else if (which == 1) {
                const size_t base = (size_t)bh * HD * SEQ;
                #pragma unroll
                for (int nf = 0; nf < 8; nf++) {
                    const int e = nf * 8 + 2 * tg;
                    g_kT[base + (size_t)(e    ) * SEQ + s] = to_tf32(acc[mf][nf][half*2+0] + bl[nf].x);
                    g_kT[base + (size_t)(e + 1) * SEQ + s] = to_tf32(acc[mf][nf][half*2+1] + bl[nf].y);
                }
            } else {
                float* dst = g_v + ((size_t)bh * SEQ + s) * HD;
                #pragma unroll
                for (int nf = 0; nf < 8; nf++) {
                    float2 o;
                    o.x = to_tf32(acc[mf][nf][half*2+0] + bl[nf].x);
                    o.y = to_tf32(acc[mf][nf][half*2+1] + bl[nf].y);
                    *(float2*)&dst[nf * 8 + 2 * tg] = o;
                }
            }
        }
    }
}

// Output projection: g_ctx[4096,1024] x Wo -> out (+bo), fp32 out.
__global__ __launch_bounds__(512) void out_mma_kernel(
    const float* __restrict__ bo, float* __restrict__ out)
{
    extern __shared__ float sm[];
    const int m0 = blockIdx.x * 256;
    const int n0 = blockIdx.y * 128;
    const int t = threadIdx.x;
    const int warp = t >> 5, lane = t & 31, g = lane >> 2, tg = lane & 3;
    const int wm = (warp >> 1) * 32, wn = (warp & 1) * 64;

    auto issue = [&](int k0, int st) {
        float* As = sm + st * G_STAGE;
        float* Bs = As + 256 * GA_STRIDE;
        #pragma unroll
        for (int j = 0; j < 4; j++) {
            const int lin = j * 512 + t;
            const int r = lin >> 3, c = (lin & 7) * 4;
            CP_ASYNC16(smem_u32(&As[r * GA_STRIDE + c]),
                       &g_ctx[(size_t)(m0 + r) * DIM + k0 + c]);
        }
        #pragma unroll
        for (int j = 0; j < 2; j++) {
            const int lin = j * 512 + t;
            const int r = lin >> 5, n = (lin & 31) * 4;
            CP_ASYNC16(smem_u32(&Bs[r * GB_STRIDE + n]),
                       &g_wo[(size_t)(k0 + r) * DIM + n0 + n]);
        }
    };

    float acc[2][8][4];
    #pragma unroll
    for (int i = 0; i < 2; i++)
        #pragma unroll
        for (int j = 0; j < 8; j++)
            #pragma unroll
            for (int c = 0; c < 4; c++) acc[i][j][c] = 0.f;

    issue(0, 0); CP_COMMIT();
    for (int it = 0; it < 32; it++) {
        CP_WAIT0(); __syncthreads();
        if (it < 31) { issue((it + 1) * 32, (it + 1) & 1); CP_COMMIT(); }
        const float* As = sm + (it & 1) * G_STAGE;
        const float* Bs = As + 256 * GA_STRIDE;
        #pragma unroll
        for (int s8 = 0; s8 < 4; s8++) {
            const int k = s8 * 8;
            uint32_t bf[8][2];
            #pragma unroll
            for (int nf = 0; nf < 8; nf++) {
                bf[nf][0] = __float_as_uint(Bs[(k + tg    ) * GB_STRIDE + wn + nf * 8 + g]);
                bf[nf][1] = __float_as_uint(Bs[(k + tg + 4) * GB_STRIDE + wn + nf * 8 + g]);
            }
            uint32_t af[2][4];
            #pragma unroll
            for (int mf = 0; mf < 2; mf++) {
                const int r = wm + mf * 16 + g;
                af[mf][0] = __float_as_uint(As[(r    ) * GA_STRIDE + k + tg    ]);
                af[mf][1] = __float_as_uint(As[(r + 8) * GA_STRIDE + k + tg    ]);
                af[mf][2] = __float_as_uint(As[(r    ) * GA_STRIDE + k + tg + 4]);
                af[mf][3] = __float_as_uint(As[(r + 8) * GA_STRIDE + k + tg + 4]);
            }
            #pragma unroll
            for (int mf = 0; mf < 2; mf++)
                #pragma unroll
                for (int nf = 0; nf < 8; nf++)
                    mma_m16n8k8(acc[mf][nf], af[mf], bf[nf]);
        }
    }

    float2 bl[8];
    #pragma unroll
    for (int nf = 0; nf < 8; nf++)
        bl[nf] = *(const float2*)&bo[n0 + wn + nf * 8 + 2 * tg];

    #pragma unroll
    for (int mf = 0; mf < 2; mf++) {
        #pragma unroll
        for (int half = 0; half < 2; half++) {
            const int m = m0 + wm + mf * 16 + g + half * 8;
            float* dst = out + (size_t)m * DIM + n0 + wn;
            #pragma unroll
            for (int nf = 0; nf < 8; nf++) {
                float2 o;
                o.x = acc[mf][nf][half*2+0] + bl[nf].x;
                o.y = acc[mf][nf][half*2+1] + bl[nf].y;
                *(float2*)&dst[nf * 8 + 2 * tg] = o;
            }
        }
    }
}

// ---------------------------------------------------------------------------
// Flash attention: Q-tile 128, KV-tile 64, 256 threads (8 warps, 16 q-rows each).
// Double-buffered K/V via cp.async. Scores arrive in log2 domain (scale folded
// into Q) -> single ex2 per score, no running max (shift-invariance).
// ---------------------------------------------------------------------------
#define FQ_STRIDE 68          // 4 mod 32: conflict-free A-frag loads
#define FK_STRIDE 72          // 8 mod 32: conflict-free B-frag loads
#define F_Q   (128*FQ_STRIDE) // 8704 floats
#define F_KV  (64*FK_STRIDE)  // 4608 floats
#define FLASH_SMEM ((2*F_Q + 2*2*F_KV) * 4)  // 143,360 B

__global__ __launch_bounds__(256) void flash_mma_kernel(const int* __restrict__ mask)
{
    extern __shared__ float sm[];
    float* Qs = sm;            // [q 128][e 64]
    float* Ps = sm + F_Q;      // [q 128][kv 64]  (warp-private rows)

    const int bh = blockIdx.y;
    const int b = bh >> 4, h = bh & 15;
    const int q0 = blockIdx.x * 128;
    const int t = threadIdx.x;
    const int warp = t >> 5, lane = t & 31, g = lane >> 2, tg = lane & 3;
    const int wm = warp * 16;

    const float* qp  = g_q  + ((size_t)bh * SEQ + q0) * HD;
    const float* kTp = g_kT + (size_t)bh * HD * SEQ;
    const float* vp  = g_v  + (size_t)bh * SEQ * HD;
    const int*   mp  = mask + (size_t)b * SEQ;

    auto issue_kv = [&](int kv0, int st) {
        float* Kt = sm + 2 * F_Q + st * 2 * F_KV;
        float* Vs = Kt + F_KV;
        #pragma unroll
        for (int j = 0; j < 4; j++) {
            const int lin = j * 256 + t;
            const int r = lin >> 4, c = (lin & 15) * 4;
            CP_ASYNC16(smem_u32(&Kt[r * FK_STRIDE + c]),
                       &kTp[(size_t)r * SEQ + kv0 + c]);
        }
        #pragma unroll
        for (int j = 0; j < 4; j++) {
            const int lin = j * 256 + t;
            const int r = lin >> 4, c = (lin & 15) * 4;
            CP_ASYNC16(smem_u32(&Vs[r * FK_STRIDE + c]),
                       &vp[(size_t)(kv0 + r) * HD + c]);
        }
    };

    // prologue: Q tile + KV tile 0 in one group
    #pragma unroll
    for (int j = 0; j < 8; j++) {
        const int lin = j * 256 + t;
        const int r = lin >> 4, c = (lin & 15) * 4;
        CP_ASYNC16(smem_u32(&Qs[r * FQ_STRIDE + c]), &qp[(size_t)r * HD + c]);
    }
    issue_kv(0, 0); CP_COMMIT();

    float ctx[8][4];
    #pragma unroll
    for (int j = 0; j < 8; j++)
        #pragma unroll
        for (int c = 0; c < 4; c++) ctx[j][c] = 0.f;
    float lrow[2] = {0.f, 0.f};

    for (int it = 0; it < SEQ / 64; it++) {
        CP_WAIT0(); __syncthreads();
        if (it < SEQ / 64 - 1) { issue_kv((it + 1) * 64, (it + 1) & 1); CP_COMMIT(); }
        const float* Kt = sm + 2 * F_Q + (it & 1) * 2 * F_KV;
        const float* Vs = Kt + F_KV;

        // --- S = Q . K^T (log2 domain) ---
        float sacc[8][4];
        #pragma unroll
        for (int j = 0; j < 8; j++)
            #pragma unroll
            for (int c = 0; c < 4; c++) sacc[j][c] = 0.f;

        #pragma unroll
        for (int s8 = 0; s8 < 8; s8++) {
            const int k = s8 * 8;
            uint32_t bf[8][2];
            #pragma unroll
            for (int nf = 0; nf < 8; nf++) {
                bf[nf][0] = __float_as_uint(Kt[(k + tg    ) * FK_STRIDE + nf * 8 + g]);
                bf[nf][1] = __float_as_uint(Kt[(k + tg + 4) * FK_STRIDE + nf * 8 + g]);
            }
            uint32_t af[4];
            const int r = wm + g;
            af[0] = __float_as_uint(Qs[(r    ) * FQ_STRIDE + k + tg    ]);
            af[1] = __float_as_uint(Qs[(r + 8) * FQ_STRIDE + k + tg    ]);
            af[2] = __float_as_uint(Qs[(r    ) * FQ_STRIDE + k + tg + 4]);
            af[3] = __float_as_uint(Qs[(r + 8) * FQ_STRIDE + k + tg + 4]);
            #pragma unroll
            for (int nf = 0; nf < 8; nf++)
                mma_m16n8k8(sacc[nf], af, bf[nf]);
        }

        // --- mask -> exp2 -> P (tf32) + l accumulation ---
        const int kvb = it * 64;
        #pragma unroll
        for (int nf = 0; nf < 8; nf++) {
            const int2 mv = *(const int2*)&mp[kvb + nf * 8 + 2 * tg];
            if (!mv.x) { sacc[nf][0] = -1e9f; sacc[nf][2] = -1e9f; }
            if (!mv.y) { sacc[nf][1] = -1e9f; sacc[nf][3] = -1e9f; }
            float p[4];
            #pragma unroll
            for (int c = 0; c < 4; c++)
                p[c] = to_tf32(ex2f(fminf(fmaxf(sacc[nf][c], -126.f), 100.f)));
            lrow[0] += p[0] + p[1];
            lrow[1] += p[2] + p[3];
            float2 o0 = make_float2(p[0], p[1]);
            float2 o1 = make_float2(p[2], p[3]);
            *(float2*)&Ps[(wm + g    ) * FQ_STRIDE + nf * 8 + 2 * tg] = o0;
            *(float2*)&Ps[(wm + g + 8) * FQ_STRIDE + nf * 8 + 2 * tg] = o1;
        }
        __syncwarp();

        // --- ctx += P . V ---
        #pragma unroll
        for (int s8 = 0; s8 < 8; s8++) {
            const int k = s8 * 8;
            uint32_t bf[8][2];
            #pragma unroll
            for (int nf = 0; nf < 8; nf++) {
                bf[nf][0] = __float_as_uint(Vs[(k + tg    ) * FK_STRIDE + nf * 8 + g]);
                bf[nf][1] = __float_as_uint(Vs[(k + tg + 4) * FK_STRIDE + nf * 8 + g]);
            }
            uint32_t af[4];
            const int r = wm + g;
            af[0] = __float_as_uint(Ps[(r    ) * FQ_STRIDE + k + tg    ]);
            af[1] = __float_as_uint(Ps[(r + 8) * FQ_STRIDE + k + tg    ]);
            af[2] = __float_as_uint(Ps[(r    ) * FQ_STRIDE + k + tg + 4]);
            af[3] = __float_as_uint(Ps[(r + 8) * FQ_STRIDE + k + tg + 4]);
            #pragma unroll
            for (int nf = 0; nf < 8; nf++)
                mma_m16n8k8(ctx[nf], af, bf[nf]);
        }
    }

    // epilogue: reduce l across the 4 lanes sharing each row, normalize, write
    #pragma unroll
    for (int half = 0; half < 2; half++) {
        float l = lrow[half];
        l += __shfl_xor_sync(0xffffffffu, l, 1, 4);
        l += __shfl_xor_sync(0xffffffffu, l, 2, 4);
        const float inv = (l > 0.f) ? 1.f / l : 0.f;
        const int q = q0 + wm + g + half * 8;
        float* dst = &g_ctx[((size_t)b * SEQ + q) * DIM + h * HD];
        #pragma unroll
        for (int nf = 0; nf < 8; nf++) {
            float2 o;
            o.x = to_tf32(ctx[nf][half*2+0] * inv);
            o.y = to_tf32(ctx[nf][half*2+1] * inv);
            *(float2*)&dst[nf * 8 + 2 * tg] = o;
        }
    }
}

// ---------------------------------------------------------------------------
extern "C" void kernel_launch(void* const* d_in, const int* in_sizes, int n_in,
                              void* d_out, int out_size)
{
    (void)in_sizes; (void)n_in; (void)out_size;
    const float* query = (const float*)d_in[0];
    const float* key   = (const float*)d_in[1];
    const float* value = (const float*)d_in[2];
    const int*   mask  = (const int*)d_in[3];
    const float* Wq = (const float*)d_in[4];
    const float* bq = (const float*)d_in[5];
    const float* Wk = (const float*)d_in[6];
    const float* bk = (const float*)d_in[7];
    const float* Wv = (const float*)d_in[8];
    const float* bv = (const float*)d_in[9];
    const float* Wo = (const float*)d_in[10];
    const float* bo = (const float*)d_in[11];
    float* out = (float*)d_out;

    cudaFuncSetAttribute(qkv_mma_kernel, cudaFuncAttributeMaxDynamicSharedMemorySize, GEMM_SMEM);
    cudaFuncSetAttribute(out_mma_kernel, cudaFuncAttributeMaxDynamicSharedMemorySize, GEMM_SMEM);
    cudaFuncSetAttribute(flash_mma_kernel, cudaFuncAttributeMaxDynamicSharedMemorySize, FLASH_SMEM);

    prep_act_kernel<<<dim3(4096, 3), 256>>>(query, key, value);
    prep_w_kernel<<<dim3(1024, 4), 256>>>(Wq, Wk, Wv, Wo);

    dim3 gQKV(M_TOT / 256, NH / 2, 3);
    qkv_mma_kernel<<<gQKV, 512, GEMM_SMEM>>>(bq, bk, bv);

    dim3 gFA(SEQ / 128, BATCH * NH);
    flash_mma_kernel<<<gFA, 256, FLASH_SMEM>>>(mask);

    dim3 gOUT(M_TOT / 256, DIM / 128);
    out_mma_kernel<<<gOUT, 512, GEMM_SMEM>>>(bo, out);
}

// round 5
// speedup vs baseline: 5.4457x; 1.0974x over previous
#include <cuda_runtime.h>
#include <math.h>
#include <stdint.h>

#define BATCH 2
#define SEQ   2048
#define DIM   1024
#define NH    16
#define HD    64
#define M_TOT (BATCH*SEQ)           // 4096
#define SCALE_Q 0.18033688011112042f  // 0.125 * log2(e): scores land in log2 domain

// ---- scratch (device globals; no cudaMalloc allowed) ----
__device__ float g_aq[(size_t)M_TOT*DIM];      // tf32-rounded activations
__device__ float g_ak[(size_t)M_TOT*DIM];
__device__ float g_av[(size_t)M_TOT*DIM];
__device__ float g_wq[(size_t)NH*DIM*HD];      // tf32-rounded weights
__device__ float g_wk[(size_t)NH*DIM*HD];
__device__ float g_wv[(size_t)NH*DIM*HD];
__device__ float g_wo[(size_t)DIM*DIM];
__device__ float g_q [(size_t)BATCH*NH*SEQ*HD]; // [bh][s][e], pre-scaled by 0.125*log2e, tf32
__device__ float g_kT[(size_t)BATCH*NH*HD*SEQ]; // [bh][e][s], tf32
__device__ float g_v [(size_t)BATCH*NH*SEQ*HD]; // [bh][s][e], tf32
__device__ float g_ctx[(size_t)M_TOT*DIM];      // [b][s][h*HD+e], tf32

// ---- helpers ----
__device__ __forceinline__ float to_tf32(float x) {
    float y; asm("cvt.rna.tf32.f32 %0, %1;" : "=f"(y) : "f"(x)); return y;
}
__device__ __forceinline__ float ex2f(float x) {
    float y; asm("ex2.approx.f32 %0, %1;" : "=f"(y) : "f"(x)); return y;
}
__device__ __forceinline__ uint32_t smem_u32(const void* p) {
    return (uint32_t)__cvta_generic_to_shared(p);
}
#define CP_ASYNC16(dst, src) \
    asm volatile("cp.async.cg.shared.global [%0], [%1], 16;" :: "r"(dst), "l"(src))
#define CP_COMMIT() asm volatile("cp.async.commit_group;")
#define CP_WAIT0()  asm volatile("cp.async.wait_group 0;")

// D += A(16x8) * B(8x8), tf32 inputs, fp32 accum.
__device__ __forceinline__ void mma_m16n8k8(float* d, const uint32_t* a, const uint32_t* b) {
    asm volatile(
        "mma.sync.aligned.m16n8k8.row.col.f32.tf32.tf32.f32 "
        "{%0,%1,%2,%3}, {%4,%5,%6,%7}, {%8,%9}, {%0,%1,%2,%3};"
        : "+f"(d[0]), "+f"(d[1]), "+f"(d[2]), "+f"(d[3])
        : "r"(a[0]), "r"(a[1]), "r"(a[2]), "r"(a[3]), "r"(b[0]), "r"(b[1]));
}

// ---------------------------------------------------------------------------
// Prep: tf32-round inputs so mainloops can cp.async raw bits.
// ---------------------------------------------------------------------------
__global__ __launch_bounds__(256) void prep_act_kernel(
    const float* __restrict__ q, const float* __restrict__ k, const float* __restrict__ v)
{
    const int z = blockIdx.y;
    const float4* s = (const float4*)(z == 0 ? q : z == 1 ? k : v);
    float4* d = (float4*)(z == 0 ? g_aq : z == 1 ? g_ak : g_av);
    const size_t i = (size_t)blockIdx.x * 256 + threadIdx.x;
    float4 x = s[i];
    d[i] = make_float4(to_tf32(x.x), to_tf32(x.y), to_tf32(x.z), to_tf32(x.w));
}
__global__ __launch_bounds__(256) void prep_w_kernel(
    const float* __restrict__ wq, const float* __restrict__ wk,
    const float* __restrict__ wv, const float* __restrict__ wo)
{
    const int z = blockIdx.y;
    const float4* s = (const float4*)(z == 0 ? wq : z == 1 ? wk : z == 2 ? wv : wo);
    float4* d = (float4*)(z == 0 ? g_wq : z == 1 ? g_wk : z == 2 ? g_wv : g_wo);
    const size_t i = (size_t)blockIdx.x * 256 + threadIdx.x;
    float4 x = s[i];
    d[i] = make_float4(to_tf32(x.x), to_tf32(x.y), to_tf32(x.z), to_tf32(x.w));
}

// ---------------------------------------------------------------------------
// GEMM: BM=256, BN=128, BK=32, 512 threads (16 warps 8x2), double-buffered.
// As [m][k] stride 36 (4 mod 32 -> conflict-free A-frags); Bs [k][n] stride 136.
// ---------------------------------------------------------------------------
#define GA_STRIDE 36
#define GB_STRIDE 136
#define G_STAGE   (256*GA_STRIDE + 32*GB_STRIDE)   // 13568 floats
#define GEMM_SMEM (2*G_STAGE*4)                    // 108,544 B

__global__ __launch_bounds__(512) void qkv_mma_kernel(
    const float* __restrict__ bq, const float* __restrict__ bk, const float* __restrict__ bv)
{
    extern __shared__ float sm[];
    const int which = blockIdx.z;
    const float* A    = which == 0 ? g_aq : which == 1 ? g_ak : g_av;
    const float* W    = which == 0 ? g_wq : which == 1 ? g_wk : g_wv;
    const float* bias = which == 0 ? bq   : which == 1 ? bk   : bv;

    const int m0 = blockIdx.x * 256;
    const int hp = blockIdx.y;
    const int t = threadIdx.x;
    const int warp = t >> 5, lane = t & 31, g = lane >> 2, tg = lane & 3;
    const int wm = (warp >> 1) * 32, wn = (warp & 1) * 64;

    const float* Wb = W + (size_t)(hp * 2) * DIM * HD;

    auto issue = [&](int k0, int st) {
        float* As = sm + st * G_STAGE;
        float* Bs = As + 256 * GA_STRIDE;
        #pragma unroll
        for (int j = 0; j < 4; j++) {
            const int lin = j * 512 + t;
            const int r = lin >> 3, c = (lin & 7) * 4;
            CP_ASYNC16(smem_u32(&As[r * GA_STRIDE + c]),
                       &A[(size_t)(m0 + r) * DIM + k0 + c]);
        }
        #pragma unroll
        for (int j = 0; j < 2; j++) {
            const int lin = j * 512 + t;
            const int r = lin >> 5, n = (lin & 31) * 4;
            CP_ASYNC16(smem_u32(&Bs[r * GB_STRIDE + n]),
                       &Wb[(size_t)(n >> 6) * DIM * HD + (size_t)(k0 + r) * HD + (n & 63)]);
        }
    };

    float acc[2][8][4];
    #pragma unroll
    for (int i = 0; i < 2; i++)
        #pragma unroll
        for (int j = 0; j < 8; j++)
            #pragma unroll
            for (int c = 0; c < 4; c++) acc[i][j][c] = 0.f;

    issue(0, 0); CP_COMMIT();
    for (int it = 0; it < 32; it++) {
        CP_WAIT0(); __syncthreads();
        if (it < 31) { issue((it + 1) * 32, (it + 1) & 1); CP_COMMIT(); }
        const float* As = sm + (it & 1) * G_STAGE;
        const float* Bs = As + 256 * GA_STRIDE;
        #pragma unroll
        for (int s8 = 0; s8 < 4; s8++) {
            const int k = s8 * 8;
            uint32_t bf[8][2];
            #pragma unroll
            for (int nf = 0; nf < 8; nf++) {
                bf[nf][0] = __float_as_uint(Bs[(k + tg    ) * GB_STRIDE + wn + nf * 8 + g]);
                bf[nf][1] = __float_as_uint(Bs[(k + tg + 4) * GB_STRIDE + wn + nf * 8 + g]);
            }
            uint32_t af[2][4];
            #pragma unroll
            for (int mf = 0; mf < 2; mf++) {
                const int r = wm + mf * 16 + g;
                af[mf][0] = __float_as_uint(As[(r    ) * GA_STRIDE + k + tg    ]);
                af[mf][1] = __float_as_uint(As[(r + 8) * GA_STRIDE + k + tg    ]);
                af[mf][2] = __float_as_uint(As[(r    ) * GA_STRIDE + k + tg + 4]);
                af[mf][3] = __float_as_uint(As[(r + 8) * GA_STRIDE + k + tg + 4]);
            }
            #pragma unroll
            for (int mf = 0; mf < 2; mf++)
                #pragma unroll
                for (int nf = 0; nf < 8; nf++)
                    mma_m16n8k8(acc[mf][nf], af[mf], bf[nf]);
        }
    }

    const int h = hp * 2 + (wn >> 6);
    float2 bl[8];
    #pragma unroll
    for (int nf = 0; nf < 8; nf++)
        bl[nf] = *(const float2*)&bias[h * HD + nf * 8 + 2 * tg];

    #pragma unroll
    for (int mf = 0; mf < 2; mf++) {
        #pragma unroll
        for (int half = 0; half < 2; half++) {
            const int m = m0 + wm + mf * 16 + g + half * 8;
            const int b = m >> 11, s = m & (SEQ - 1);
            const int bh = b * NH + h;
            if (which == 0) {
                float* dst = g_q + ((size_t)bh * SEQ + s) * HD;
                #pragma unroll
                for (int nf = 0; nf < 8; nf++) {
                    float2 o;
                    o.x = to_tf32((acc[mf][nf][half*2+0] + bl[nf].x) * SCALE_Q);
                    o.y = to_tf32((acc[mf][nf][half*2+1] + bl[nf].y) * SCALE_Q);
                    *(float2*)&dst[nf * 8 + 2 * tg] = o;
                }
            } else if (which == 1) {
                const size_t base = (size_t)bh * HD * SEQ;
                #pragma unroll
                for (int nf = 0; nf < 8; nf++) {
                    const int e = nf * 8 + 2 * tg;
                    g_kT[base + (size_t)(e    ) * SEQ + s] = to_tf32(acc[mf][nf][half*2+0] + bl[nf].x);
                    g_kT[base + (size_t)(e + 1) * SEQ + s] = to_tf32(acc[mf][nf][half*2+1] + bl[nf].y);
                }
            } else {
                float* dst = g_v + ((size_t)bh * SEQ + s) * HD;
                #pragma unroll
                for (int nf = 0; nf < 8; nf++) {
                    float2 o;
                    o.x = to_tf32(acc[mf][nf][half*2+0] + bl[nf].x);
                    o.y = to_tf32(acc[mf][nf][half*2+1] + bl[nf].y);
                    *(float2*)&dst[nf * 8 + 2 * tg] = o;
                }
            }
        }
    }
}

__global__ __launch_bounds__(512) void out_mma_kernel(
    const float* __restrict__ bo, float* __restrict__ out)
{
    extern __shared__ float sm[];
    const int m0 = blockIdx.x * 256;
    const int n0 = blockIdx.y * 128;
    const int t = threadIdx.x;
    const int warp = t >> 5, lane = t & 31, g = lane >> 2, tg = lane & 3;
    const int wm = (warp >> 1) * 32, wn = (warp & 1) * 64;

    auto issue = [&](int k0, int st) {
        float* As = sm + st * G_STAGE;
        float* Bs = As + 256 * GA_STRIDE;
        #pragma unroll
        for (int j = 0; j < 4; j++) {
            const int lin = j * 512 + t;
            const int r = lin >> 3, c = (lin & 7) * 4;
            CP_ASYNC16(smem_u32(&As[r * GA_STRIDE + c]),
                       &g_ctx[(size_t)(m0 + r) * DIM + k0 + c]);
        }
        #pragma unroll
        for (int j = 0; j < 2; j++) {
            const int lin = j * 512 + t;
            const int r = lin >> 5, n = (lin & 31) * 4;
            CP_ASYNC16(smem_u32(&Bs[r * GB_STRIDE + n]),
                       &g_wo[(size_t)(k0 + r) * DIM + n0 + n]);
        }
    };

    float acc[2][8][4];
    #pragma unroll
    for (int i = 0; i < 2; i++)
        #pragma unroll
        for (int j = 0; j < 8; j++)
            #pragma unroll
            for (int c = 0; c < 4; c++) acc[i][j][c] = 0.f;

    issue(0, 0); CP_COMMIT();
    for (int it = 0; it < 32; it++) {
        CP_WAIT0(); __syncthreads();
        if (it < 31) { issue((it + 1) * 32, (it + 1) & 1); CP_COMMIT(); }
        const float* As = sm + (it & 1) * G_STAGE;
        const float* Bs = As + 256 * GA_STRIDE;
        #pragma unroll
        for (int s8 = 0; s8 < 4; s8++) {
            const int k = s8 * 8;
            uint32_t bf[8][2];
            #pragma unroll
            for (int nf = 0; nf < 8; nf++) {
                bf[nf][0] = __float_as_uint(Bs[(k + tg    ) * GB_STRIDE + wn + nf * 8 + g]);
                bf[nf][1] = __float_as_uint(Bs[(k + tg + 4) * GB_STRIDE + wn + nf * 8 + g]);
            }
            uint32_t af[2][4];
            #pragma unroll
            for (int mf = 0; mf < 2; mf++) {
                const int r = wm + mf * 16 + g;
                af[mf][0] = __float_as_uint(As[(r    ) * GA_STRIDE + k + tg    ]);
                af[mf][1] = __float_as_uint(As[(r + 8) * GA_STRIDE + k + tg    ]);
                af[mf][2] = __float_as_uint(As[(r    ) * GA_STRIDE + k + tg + 4]);
                af[mf][3] = __float_as_uint(As[(r + 8) * GA_STRIDE + k + tg + 4]);
            }
            #pragma unroll
            for (int mf = 0; mf < 2; mf++)
                #pragma unroll
                for (int nf = 0; nf < 8; nf++)
                    mma_m16n8k8(acc[mf][nf], af[mf], bf[nf]);
        }
    }

    float2 bl[8];
    #pragma unroll
    for (int nf = 0; nf < 8; nf++)
        bl[nf] = *(const float2*)&bo[n0 + wn + nf * 8 + 2 * tg];

    #pragma unroll
    for (int mf = 0; mf < 2; mf++) {
        #pragma unroll
        for (int half = 0; half < 2; half++) {
            const int m = m0 + wm + mf * 16 + g + half * 8;
            float* dst = out + (size_t)m * DIM + n0 + wn;
            #pragma unroll
            for (int nf = 0; nf < 8; nf++) {
                float2 o;
                o.x = acc[mf][nf][half*2+0] + bl[nf].x;
                o.y = acc[mf][nf][half*2+1] + bl[nf].y;
                *(float2*)&dst[nf * 8 + 2 * tg] = o;
            }
        }
    }
}

// ---------------------------------------------------------------------------
// Flash attention: Q-tile 256, KV-tile 64, 512 threads (16 warps x 16 q-rows).
// Double-buffered K/V via cp.async. Scores arrive in log2 domain (scale folded
// into Q) -> single ex2 per score, no running max (shift-invariance).
// ---------------------------------------------------------------------------
#define FQ_STRIDE 68          // 4 mod 32: conflict-free A-frag loads
#define FK_STRIDE 72          // 8 mod 32: conflict-free B-frag loads
#define F_Q   (256*FQ_STRIDE) // 17408 floats
#define F_KV  (64*FK_STRIDE)  // 4608 floats
#define FLASH_SMEM ((2*F_Q + 2*2*F_KV) * 4)  // 212,992 B

__global__ __launch_bounds__(512) void flash_mma_kernel(const int* __restrict__ mask)
{
    extern __shared__ float sm[];
    float* Qs = sm;            // [q 256][e 64]
    float* Ps = sm + F_Q;      // [q 256][kv 64]  (warp-private rows)

    const int bh = blockIdx.y;
    const int b = bh >> 4, h = bh & 15;
    const int q0 = blockIdx.x * 256;
    const int t = threadIdx.x;
    const int warp = t >> 5, lane = t & 31, g = lane >> 2, tg = lane & 3;
    const int wm = warp * 16;

    const float* qp  = g_q  + ((size_t)bh * SEQ + q0) * HD;
    const float* kTp = g_kT + (size_t)bh * HD * SEQ;
    const float* vp  = g_v  + (size_t)bh * SEQ * HD;
    const int*   mp  = mask + (size_t)b * SEQ;

    auto issue_kv = [&](int kv0, int st) {
        float* Kt = sm + 2 * F_Q + st * 2 * F_KV;
        float* Vs = Kt + F_KV;
        #pragma unroll
        for (int j = 0; j < 2; j++) {
            const int lin = j * 512 + t;
            const int r = lin >> 4, c = (lin & 15) * 4;
            CP_ASYNC16(smem_u32(&Kt[r * FK_STRIDE + c]),
                       &kTp[(size_t)r * SEQ + kv0 + c]);
        }
        #pragma unroll
        for (int j = 0; j < 2; j++) {
            const int lin = j * 512 + t;
            const int r = lin >> 4, c = (lin & 15) * 4;
            CP_ASYNC16(smem_u32(&Vs[r * FK_STRIDE + c]),
                       &vp[(size_t)(kv0 + r) * HD + c]);
        }
    };

    // prologue: Q tile + KV tile 0 in one group
    #pragma unroll
    for (int j = 0; j < 8; j++) {
        const int lin = j * 512 + t;
        const int r = lin >> 4, c = (lin & 15) * 4;
        CP_ASYNC16(smem_u32(&Qs[r * FQ_STRIDE + c]), &qp[(size_t)r * HD + c]);
    }
    issue_kv(0, 0); CP_COMMIT();

    float ctx[8][4];
    #pragma unroll
    for (int j = 0; j < 8; j++)
        #pragma unroll
        for (int c = 0; c < 4; c++) ctx[j][c] = 0.f;
    float lrow[2] = {0.f, 0.f};

    for (int it = 0; it < SEQ / 64; it++) {
        CP_WAIT0(); __syncthreads();
        if (it < SEQ / 64 - 1) { issue_kv((it + 1) * 64, (it + 1) & 1); CP_COMMIT(); }
        const float* Kt = sm + 2 * F_Q + (it & 1) * 2 * F_KV;
        const float* Vs = Kt + F_KV;

        // --- S = Q . K^T (log2 domain) ---
        float sacc[8][4];
        #pragma unroll
        for (int j = 0; j < 8; j++)
            #pragma unroll
            for (int c = 0; c < 4; c++) sacc[j][c] = 0.f;

        #pragma unroll
        for (int s8 = 0; s8 < 8; s8++) {
            const int k = s8 * 8;
            uint32_t bf[8][2];
            #pragma unroll
            for (int nf = 0; nf < 8; nf++) {
                bf[nf][0] = __float_as_uint(Kt[(k + tg    ) * FK_STRIDE + nf * 8 + g]);
                bf[nf][1] = __float_as_uint(Kt[(k + tg + 4) * FK_STRIDE + nf * 8 + g]);
            }
            uint32_t af[4];
            const int r = wm + g;
            af[0] = __float_as_uint(Qs[(r    ) * FQ_STRIDE + k + tg    ]);
            af[1] = __float_as_uint(Qs[(r + 8) * FQ_STRIDE + k + tg    ]);
            af[2] = __float_as_uint(Qs[(r    ) * FQ_STRIDE + k + tg + 4]);
            af[3] = __float_as_uint(Qs[(r + 8) * FQ_STRIDE + k + tg + 4]);
            #pragma unroll
            for (int nf = 0; nf < 8; nf++)
                mma_m16n8k8(sacc[nf], af, bf[nf]);
        }

        // --- mask -> exp2 -> P (tf32) + l accumulation ---
        const int kvb = it * 64;
        #pragma unroll
        for (int nf = 0; nf < 8; nf++) {
            const int2 mv = *(const int2*)&mp[kvb + nf * 8 + 2 * tg];
            if (!mv.x) { sacc[nf][0] = -1e9f; sacc[nf][2] = -1e9f; }
            if (!mv.y) { sacc[nf][1] = -1e9f; sacc[nf][3] = -1e9f; }
            float p[4];
            #pragma unroll
            for (int c = 0; c < 4; c++)
                p[c] = to_tf32(ex2f(sacc[nf][c]));   // ex2(-1e9) underflows to +0
            lrow[0] += p[0] + p[1];
            lrow[1] += p[2] + p[3];
            float2 o0 = make_float2(p[0], p[1]);
            float2 o1 = make_float2(p[2], p[3]);
            *(float2*)&Ps[(wm + g    ) * FQ_STRIDE + nf * 8 + 2 * tg] = o0;
            *(float2*)&Ps[(wm + g + 8) * FQ_STRIDE + nf * 8 + 2 * tg] = o1;
        }
        __syncwarp();

        // --- ctx += P . V ---
        #pragma unroll
        for (int s8 = 0; s8 < 8; s8++) {
            const int k = s8 * 8;
            uint32_t bf[8][2];
            #pragma unroll
            for (int nf = 0; nf < 8; nf++) {
                bf[nf][0] = __float_as_uint(Vs[(k + tg    ) * FK_STRIDE + nf * 8 + g]);
                bf[nf][1] = __float_as_uint(Vs[(k + tg + 4) * FK_STRIDE + nf * 8 + g]);
            }
            uint32_t af[4];
            const int r = wm + g;
            af[0] = __float_as_uint(Ps[(r    ) * FQ_STRIDE + k + tg    ]);
            af[1] = __float_as_uint(Ps[(r + 8) * FQ_STRIDE + k + tg    ]);
            af[2] = __float_as_uint(Ps[(r    ) * FQ_STRIDE + k + tg + 4]);
            af[3] = __float_as_uint(Ps[(r + 8) * FQ_STRIDE + k + tg + 4]);
            #pragma unroll
            for (int nf = 0; nf < 8; nf++)
                mma_m16n8k8(ctx[nf], af, bf[nf]);
        }
    }

    // epilogue: reduce l across the 4 lanes sharing each row, normalize, write
    #pragma unroll
    for (int half = 0; half < 2; half++) {
        float l = lrow[half];
        l += __shfl_xor_sync(0xffffffffu, l, 1, 4);
        l += __shfl_xor_sync(0xffffffffu, l, 2, 4);
        const float inv = (l > 0.f) ? 1.f / l : 0.f;
        const int q = q0 + wm + g + half * 8;
        float* dst = &g_ctx[((size_t)b * SEQ + q) * DIM + h * HD];
        #pragma unroll
        for (int nf = 0; nf < 8; nf++) {
            float2 o;
            o.x = to_tf32(ctx[nf][half*2+0] * inv);
            o.y = to_tf32(ctx[nf][half*2+1] * inv);
            *(float2*)&dst[nf * 8 + 2 * tg] = o;
        }
    }
}

// ---------------------------------------------------------------------------
extern "C" void kernel_launch(void* const* d_in, const int* in_sizes, int n_in,
                              void* d_out, int out_size)
{
    (void)in_sizes; (void)n_in; (void)out_size;
    const float* query = (const float*)d_in[0];
    const float* key   = (const float*)d_in[1];
    const float* value = (const float*)d_in[2];
    const int*   mask  = (const int*)d_in[3];
    const float* Wq = (const float*)d_in[4];
    const float* bq = (const float*)d_in[5];
    const float* Wk = (const float*)d_in[6];
    const float* bk = (const float*)d_in[7];
    const float* Wv = (const float*)d_in[8];
    const float* bv = (const float*)d_in[9];
    const float* Wo = (const float*)d_in[10];
    const float* bo = (const float*)d_in[11];
    float* out = (float*)d_out;

    cudaFuncSetAttribute(qkv_mma_kernel, cudaFuncAttributeMaxDynamicSharedMemorySize, GEMM_SMEM);
    cudaFuncSetAttribute(out_mma_kernel, cudaFuncAttributeMaxDynamicSharedMemorySize, GEMM_SMEM);
    cudaFuncSetAttribute(flash_mma_kernel, cudaFuncAttributeMaxDynamicSharedMemorySize, FLASH_SMEM);

    prep_act_kernel<<<dim3(4096, 3), 256>>>(query, key, value);
    prep_w_kernel<<<dim3(1024, 4), 256>>>(Wq, Wk, Wv, Wo);

    dim3 gQKV(M_TOT / 256, NH / 2, 3);
    qkv_mma_kernel<<<gQKV, 512, GEMM_SMEM>>>(bq, bk, bv);

    dim3 gFA(SEQ / 256, BATCH * NH);
    flash_mma_kernel<<<gFA, 512, FLASH_SMEM>>>(mask);

    dim3 gOUT(M_TOT / 256, DIM / 128);
    out_mma_kernel<<<gOUT, 512, GEMM_SMEM>>>(bo, out);
}

// round 6
// speedup vs baseline: 5.6174x; 1.0315x over previous
#include <cuda_runtime.h>
#include <math.h>
#include <stdint.h>

#define BATCH 2
#define SEQ   2048
#define DIM   1024
#define NH    16
#define HD    64
#define M_TOT (BATCH*SEQ)           // 4096
#define SCALE_Q 0.18033688011112042f  // 0.125 * log2(e): scores land in log2 domain

// ---- scratch (device globals; no cudaMalloc allowed) ----
__device__ float g_aq[(size_t)M_TOT*DIM];      // tf32-rounded activations
__device__ float g_ak[(size_t)M_TOT*DIM];
__device__ float g_av[(size_t)M_TOT*DIM];
__device__ float g_wq[(size_t)NH*DIM*HD];      // tf32-rounded weights
__device__ float g_wk[(size_t)NH*DIM*HD];
__device__ float g_wv[(size_t)NH*DIM*HD];
__device__ float g_wo[(size_t)DIM*DIM];
__device__ float g_q [(size_t)BATCH*NH*SEQ*HD]; // [bh][s][e], pre-scaled by 0.125*log2e, tf32
__device__ float g_kT[(size_t)BATCH*NH*HD*SEQ]; // [bh][e][s], tf32
__device__ float g_v [(size_t)BATCH*NH*SEQ*HD]; // [bh][s][e], tf32
__device__ float g_ctx[(size_t)M_TOT*DIM];      // [b][s][h*HD+e], tf32

// ---- helpers ----
__device__ __forceinline__ float to_tf32(float x) {
    float y; asm("cvt.rna.tf32.f32 %0, %1;" : "=f"(y) : "f"(x)); return y;
}
__device__ __forceinline__ float ex2f(float x) {
    float y; asm("ex2.approx.f32 %0, %1;" : "=f"(y) : "f"(x)); return y;
}
__device__ __forceinline__ uint32_t smem_u32(const void* p) {
    return (uint32_t)__cvta_generic_to_shared(p);
}
#define CP_ASYNC16(dst, src) \
    asm volatile("cp.async.cg.shared.global [%0], [%1], 16;" :: "r"(dst), "l"(src))
#define CP_COMMIT() asm volatile("cp.async.commit_group;")
#define CP_WAIT0()  asm volatile("cp.async.wait_group 0;")

// D += A(16x8) * B(8x8), tf32 inputs, fp32 accum.
__device__ __forceinline__ void mma_m16n8k8(float* d, const uint32_t* a, const uint32_t* b) {
    asm volatile(
        "mma.sync.aligned.m16n8k8.row.col.f32.tf32.tf32.f32 "
        "{%0,%1,%2,%3}, {%4,%5,%6,%7}, {%8,%9}, {%0,%1,%2,%3};"
        : "+f"(d[0]), "+f"(d[1]), "+f"(d[2]), "+f"(d[3])
        : "r"(a[0]), "r"(a[1]), "r"(a[2]), "r"(a[3]), "r"(b[0]), "r"(b[1]));
}

// ---------------------------------------------------------------------------
// Prep: tf32-round inputs so mainloops can cp.async raw bits.
// ---------------------------------------------------------------------------
__global__ __launch_bounds__(256) void prep_act_kernel(
    const float* __restrict__ q, const float* __restrict__ k, const float* __restrict__ v)
{
    const int z = blockIdx.y;
    const float4* s = (const float4*)(z == 0 ? q : z == 1 ? k : v);
    float4* d = (float4*)(z == 0 ? g_aq : z == 1 ? g_ak : g_av);
    const size_t i = (size_t)blockIdx.x * 256 + threadIdx.x;
    float4 x = s[i];
    d[i] = make_float4(to_tf32(x.x), to_tf32(x.y), to_tf32(x.z), to_tf32(x.w));
}
__global__ __launch_bounds__(256) void prep_w_kernel(
    const float* __restrict__ wq, const float* __restrict__ wk,
    const float* __restrict__ wv, const float* __restrict__ wo)
{
    const int z = blockIdx.y;
    const float4* s = (const float4*)(z == 0 ? wq : z == 1 ? wk : z == 2 ? wv : wo);
    float4* d = (float4*)(z == 0 ? g_wq : z == 1 ? g_wk : z == 2 ? g_wv : g_wo);
    const size_t i = (size_t)blockIdx.x * 256 + threadIdx.x;
    float4 x = s[i];
    d[i] = make_float4(to_tf32(x.x), to_tf32(x.y), to_tf32(x.z), to_tf32(x.w));
}

// ---------------------------------------------------------------------------
// GEMM: BM=256, BN=128, BK=32, 512 threads (16 warps 8x2), double-buffered.
// ---------------------------------------------------------------------------
#define GA_STRIDE 36
#define GB_STRIDE 136
#define G_STAGE   (256*GA_STRIDE + 32*GB_STRIDE)   // 13568 floats
#define GEMM_SMEM (2*G_STAGE*4)                    // 108,544 B

__global__ __launch_bounds__(512) void qkv_mma_kernel(
    const float* __restrict__ bq, const float* __restrict__ bk, const float* __restrict__ bv)
{
    extern __shared__ float sm[];
    const int which = blockIdx.z;
    const float* A    = which == 0 ? g_aq : which == 1 ? g_ak : g_av;
    const float* W    = which == 0 ? g_wq : which == 1 ? g_wk : g_wv;
    const float* bias = which == 0 ? bq   : which == 1 ? bk   : bv;

    const int m0 = blockIdx.x * 256;
    const int hp = blockIdx.y;
    const int t = threadIdx.x;
    const int warp = t >> 5, lane = t & 31, g = lane >> 2, tg = lane & 3;
    const int wm = (warp >> 1) * 32, wn = (warp & 1) * 64;

    const float* Wb = W + (size_t)(hp * 2) * DIM * HD;

    auto issue = [&](int k0, int st) {
        float* As = sm + st * G_STAGE;
        float* Bs = As + 256 * GA_STRIDE;
        #pragma unroll
        for (int j = 0; j < 4; j++) {
            const int lin = j * 512 + t;
            const int r = lin >> 3, c = (lin & 7) * 4;
            CP_ASYNC16(smem_u32(&As[r * GA_STRIDE + c]),
                       &A[(size_t)(m0 + r) * DIM + k0 + c]);
        }
        #pragma unroll
        for (int j = 0; j < 2; j++) {
            const int lin = j * 512 + t;
            const int r = lin >> 5, n = (lin & 31) * 4;
            CP_ASYNC16(smem_u32(&Bs[r * GB_STRIDE + n]),
                       &Wb[(size_t)(n >> 6) * DIM * HD + (size_t)(k0 + r) * HD + (n & 63)]);
        }
    };

    float acc[2][8][4];
    #pragma unroll
    for (int i = 0; i < 2; i++)
        #pragma unroll
        for (int j = 0; j < 8; j++)
            #pragma unroll
            for (int c = 0; c < 4; c++) acc[i][j][c] = 0.f;

    issue(0, 0); CP_COMMIT();
    for (int it = 0; it < 32; it++) {
        CP_WAIT0(); __syncthreads();
        if (it < 31) { issue((it + 1) * 32, (it + 1) & 1); CP_COMMIT(); }
        const float* As = sm + (it & 1) * G_STAGE;
        const float* Bs = As + 256 * GA_STRIDE;
        #pragma unroll
        for (int s8 = 0; s8 < 4; s8++) {
            const int k = s8 * 8;
            uint32_t bf[8][2];
            #pragma unroll
            for (int nf = 0; nf < 8; nf++) {
                bf[nf][0] = __float_as_uint(Bs[(k + tg    ) * GB_STRIDE + wn + nf * 8 + g]);
                bf[nf][1] = __float_as_uint(Bs[(k + tg + 4) * GB_STRIDE + wn + nf * 8 + g]);
            }
            uint32_t af[2][4];
            #pragma unroll
            for (int mf = 0; mf < 2; mf++) {
                const int r = wm + mf * 16 + g;
                af[mf][0] = __float_as_uint(As[(r    ) * GA_STRIDE + k + tg    ]);
                af[mf][1] = __float_as_uint(As[(r + 8) * GA_STRIDE + k + tg    ]);
                af[mf][2] = __float_as_uint(As[(r    ) * GA_STRIDE + k + tg + 4]);
                af[mf][3] = __float_as_uint(As[(r + 8) * GA_STRIDE + k + tg + 4]);
            }
            #pragma unroll
            for (int mf = 0; mf < 2; mf++)
                #pragma unroll
                for (int nf = 0; nf < 8; nf++)
                    mma_m16n8k8(acc[mf][nf], af[mf], bf[nf]);
        }
    }

    const int h = hp * 2 + (wn >> 6);
    float2 bl[8];
    #pragma unroll
    for (int nf = 0; nf < 8; nf++)
        bl[nf] = *(const float2*)&bias[h * HD + nf * 8 + 2 * tg];

    #pragma unroll
    for (int mf = 0; mf < 2; mf++) {
        #pragma unroll
        for (int half = 0; half < 2; half++) {
            const int m = m0 + wm + mf * 16 + g + half * 8;
            const int b = m >> 11, s = m & (SEQ - 1);
            const int bh = b * NH + h;
            if (which == 0) {
                float* dst = g_q + ((size_t)bh * SEQ + s) * HD;
                #pragma unroll
                for (int nf = 0; nf < 8; nf++) {
                    float2 o;
                    o.x = to_tf32((acc[mf][nf][half*2+0] + bl[nf].x) * SCALE_Q);
                    o.y = to_tf32((acc[mf][nf][half*2+1] + bl[nf].y) * SCALE_Q);
                    *(float2*)&dst[nf * 8 + 2 * tg] = o;
                }
            } else if (which == 1) {
                const size_t base = (size_t)bh * HD * SEQ;
                #pragma unroll
                for (int nf = 0; nf < 8; nf++) {
                    const int e = nf * 8 + 2 * tg;
                    g_kT[base + (size_t)(e    ) * SEQ + s] = to_tf32(acc[mf][nf][half*2+0] + bl[nf].x);
                    g_kT[base + (size_t)(e + 1) * SEQ + s] = to_tf32(acc[mf][nf][half*2+1] + bl[nf].y);
                }
            } else {
                float* dst = g_v + ((size_t)bh * SEQ + s) * HD;
                #pragma unroll
                for (int nf = 0; nf < 8; nf++) {
                    float2 o;
                    o.x = to_tf32(acc[mf][nf][half*2+0] + bl[nf].x);
                    o.y = to_tf32(acc[mf][nf][half*2+1] + bl[nf].y);
                    *(float2*)&dst[nf * 8 + 2 * tg] = o;
                }
            }
        }
    }
}

__global__ __launch_bounds__(512) void out_mma_kernel(
    const float* __restrict__ bo, float* __restrict__ out)
{
    extern __shared__ float sm[];
    const int m0 = blockIdx.x * 256;
    const int n0 = blockIdx.y * 128;
    const int t = threadIdx.x;
    const int warp = t >> 5, lane = t & 31, g = lane >> 2, tg = lane & 3;
    const int wm = (warp >> 1) * 32, wn = (warp & 1) * 64;

    auto issue = [&](int k0, int st) {
        float* As = sm + st * G_STAGE;
        float* Bs = As + 256 * GA_STRIDE;
        #pragma unroll
        for (int j = 0; j < 4; j++) {
            const int lin = j * 512 + t;
            const int r = lin >> 3, c = (lin & 7) * 4;
            CP_ASYNC16(smem_u32(&As[r * GA_STRIDE + c]),
                       &g_ctx[(size_t)(m0 + r) * DIM + k0 + c]);
        }
        #pragma unroll
        for (int j = 0; j < 2; j++) {
            const int lin = j * 512 + t;
            const int r = lin >> 5, n = (lin & 31) * 4;
            CP_ASYNC16(smem_u32(&Bs[r * GB_STRIDE + n]),
                       &g_wo[(size_t)(k0 + r) * DIM + n0 + n]);
        }
    };

    float acc[2][8][4];
    #pragma unroll
    for (int i = 0; i < 2; i++)
        #pragma unroll
        for (int j = 0; j < 8; j++)
            #pragma unroll
            for (int c = 0; c < 4; c++) acc[i][j][c] = 0.f;

    issue(0, 0); CP_COMMIT();
    for (int it = 0; it < 32; it++) {
        CP_WAIT0(); __syncthreads();
        if (it < 31) { issue((it + 1) * 32, (it + 1) & 1); CP_COMMIT(); }
        const float* As = sm + (it & 1) * G_STAGE;
        const float* Bs = As + 256 * GA_STRIDE;
        #pragma unroll
        for (int s8 = 0; s8 < 4; s8++) {
            const int k = s8 * 8;
            uint32_t bf[8][2];
            #pragma unroll
            for (int nf = 0; nf < 8; nf++) {
                bf[nf][0] = __float_as_uint(Bs[(k + tg    ) * GB_STRIDE + wn + nf * 8 + g]);
                bf[nf][1] = __float_as_uint(Bs[(k + tg + 4) * GB_STRIDE + wn + nf * 8 + g]);
            }
            uint32_t af[2][4];
            #pragma unroll
            for (int mf = 0; mf < 2; mf++) {
                const int r = wm + mf * 16 + g;
                af[mf][0] = __float_as_uint(As[(r    ) * GA_STRIDE + k + tg    ]);
                af[mf][1] = __float_as_uint(As[(r + 8) * GA_STRIDE + k + tg    ]);
                af[mf][2] = __float_as_uint(As[(r    ) * GA_STRIDE + k + tg + 4]);
                af[mf][3] = __float_as_uint(As[(r + 8) * GA_STRIDE + k + tg + 4]);
            }
            #pragma unroll
            for (int mf = 0; mf < 2; mf++)
                #pragma unroll
                for (int nf = 0; nf < 8; nf++)
                    mma_m16n8k8(acc[mf][nf], af[mf], bf[nf]);
        }
    }

    float2 bl[8];
    #pragma unroll
    for (int nf = 0; nf < 8; nf++)
        bl[nf] = *(const float2*)&bo[n0 + wn + nf * 8 + 2 * tg];

    #pragma unroll
    for (int mf = 0; mf < 2; mf++) {
        #pragma unroll
        for (int half = 0; half < 2; half++) {
            const int m = m0 + wm + mf * 16 + g + half * 8;
            float* dst = out + (size_t)m * DIM + n0 + wn;
            #pragma unroll
            for (int nf = 0; nf < 8; nf++) {
                float2 o;
                o.x = acc[mf][nf][half*2+0] + bl[nf].x;
                o.y = acc[mf][nf][half*2+1] + bl[nf].y;
                *(float2*)&dst[nf * 8 + 2 * tg] = o;
            }
        }
    }
}

// ---------------------------------------------------------------------------
// Flash attention: Q-tile 128, KV-tile 64, 256 threads (8 warps x 16 q-rows),
// TWO CTAs per SM (smem 108.5KB, regs forced <=128). Q fragments live in
// registers (loaded once via a staging pass through the KV smem area).
// Log2-domain softmax (scale folded into Q), no running max.
// ---------------------------------------------------------------------------
#define FQ_STRIDE 68          // 4 mod 32: conflict-free A-frag addressing
#define FK_STRIDE 72          // 8 mod 32: conflict-free B-frag loads
#define F_P   (128*FQ_STRIDE) // 8704 floats (Ps)
#define F_KV  (2*64*FK_STRIDE)// 9216 floats per stage (K + V)
#define FLASH_SMEM ((F_P + 2*F_KV) * 4)   // 108,544 B

__global__ __launch_bounds__(256, 2) void flash_mma_kernel(const int* __restrict__ mask)
{
    extern __shared__ float sm[];
    float* Ps = sm;                 // [q 128][kv 64] stride 68 (warp-private rows)
    float* KV = sm + F_P;           // 2 stages x (Kt [64][72] + Vs [64][72])

    const int bh = blockIdx.y;
    const int b = bh >> 4, h = bh & 15;
    const int q0 = blockIdx.x * 128;
    const int t = threadIdx.x;
    const int warp = t >> 5, lane = t & 31, g = lane >> 2, tg = lane & 3;
    const int wm = warp * 16;

    const float* qp  = g_q  + ((size_t)bh * SEQ + q0) * HD;
    const float* kTp = g_kT + (size_t)bh * HD * SEQ;
    const float* vp  = g_v  + (size_t)bh * SEQ * HD;
    const int*   mp  = mask + (size_t)b * SEQ;

    // ---- Stage Q through KV area once; hoist fragments to registers ----
    {
        float* Qs = KV;   // reuse stage-0 area (9216 >= 8704 floats)
        #pragma unroll
        for (int j = 0; j < 8; j++) {
            const int lin = j * 256 + t;
            const int r = lin >> 4, c = (lin & 15) * 4;
            CP_ASYNC16(smem_u32(&Qs[r * FQ_STRIDE + c]), &qp[(size_t)r * HD + c]);
        }
        CP_COMMIT(); CP_WAIT0();
        __syncthreads();
    }
    uint32_t qf[8][4];
    {
        const float* Qs = KV;
        const int r = wm + g;
        #pragma unroll
        for (int s8 = 0; s8 < 8; s8++) {
            const int k = s8 * 8;
            qf[s8][0] = __float_as_uint(Qs[(r    ) * FQ_STRIDE + k + tg    ]);
            qf[s8][1] = __float_as_uint(Qs[(r + 8) * FQ_STRIDE + k + tg    ]);
            qf[s8][2] = __float_as_uint(Qs[(r    ) * FQ_STRIDE + k + tg + 4]);
            qf[s8][3] = __float_as_uint(Qs[(r + 8) * FQ_STRIDE + k + tg + 4]);
        }
        __syncthreads();   // everyone done reading before KV prologue overwrites
    }

    auto issue_kv = [&](int kv0, int st) {
        float* Kt = KV + st * F_KV;
        float* Vs = Kt + 64 * FK_STRIDE;
        #pragma unroll
        for (int j = 0; j < 4; j++) {
            const int lin = j * 256 + t;
            const int r = lin >> 4, c = (lin & 15) * 4;
            CP_ASYNC16(smem_u32(&Kt[r * FK_STRIDE + c]),
                       &kTp[(size_t)r * SEQ + kv0 + c]);
        }
        #pragma unroll
        for (int j = 0; j < 4; j++) {
            const int lin = j * 256 + t;
            const int r = lin >> 4, c = (lin & 15) * 4;
            CP_ASYNC16(smem_u32(&Vs[r * FK_STRIDE + c]),
                       &vp[(size_t)(kv0 + r) * HD + c]);
        }
    };

    issue_kv(0, 0); CP_COMMIT();

    float ctx[8][4];
    #pragma unroll
    for (int j = 0; j < 8; j++)
        #pragma unroll
        for (int c = 0; c < 4; c++) ctx[j][c] = 0.f;
    float lrow[2] = {0.f, 0.f};

    for (int it = 0; it < SEQ / 64; it++) {
        CP_WAIT0(); __syncthreads();
        if (it < SEQ / 64 - 1) { issue_kv((it + 1) * 64, (it + 1) & 1); CP_COMMIT(); }
        const float* Kt = KV + (it & 1) * F_KV;
        const float* Vs = Kt + 64 * FK_STRIDE;

        // --- S = Q . K^T (log2 domain), A from registers ---
        float sacc[8][4];
        #pragma unroll
        for (int j = 0; j < 8; j++)
            #pragma unroll
            for (int c = 0; c < 4; c++) sacc[j][c] = 0.f;

        #pragma unroll
        for (int s8 = 0; s8 < 8; s8++) {
            const int k = s8 * 8;
            uint32_t bf[8][2];
            #pragma unroll
            for (int nf = 0; nf < 8; nf++) {
                bf[nf][0] = __float_as_uint(Kt[(k + tg    ) * FK_STRIDE + nf * 8 + g]);
                bf[nf][1] = __float_as_uint(Kt[(k + tg + 4) * FK_STRIDE + nf * 8 + g]);
            }
            #pragma unroll
            for (int nf = 0; nf < 8; nf++)
                mma_m16n8k8(sacc[nf], qf[s8], bf[nf]);
        }

        // --- mask -> exp2 -> P (tf32) + l accumulation ---
        const int kvb = it * 64;
        #pragma unroll
        for (int nf = 0; nf < 8; nf++) {
            const int2 mv = *(const int2*)&mp[kvb + nf * 8 + 2 * tg];
            if (!mv.x) { sacc[nf][0] = -1e9f; sacc[nf][2] = -1e9f; }
            if (!mv.y) { sacc[nf][1] = -1e9f; sacc[nf][3] = -1e9f; }
            float p[4];
            #pragma unroll
            for (int c = 0; c < 4; c++)
                p[c] = to_tf32(ex2f(sacc[nf][c]));   // ex2(-1e9) underflows to +0
            lrow[0] += p[0] + p[1];
            lrow[1] += p[2] + p[3];
            float2 o0 = make_float2(p[0], p[1]);
            float2 o1 = make_float2(p[2], p[3]);
            *(float2*)&Ps[(wm + g    ) * FQ_STRIDE + nf * 8 + 2 * tg] = o0;
            *(float2*)&Ps[(wm + g + 8) * FQ_STRIDE + nf * 8 + 2 * tg] = o1;
        }
        __syncwarp();

        // --- ctx += P . V ---
        #pragma unroll
        for (int s8 = 0; s8 < 8; s8++) {
            const int k = s8 * 8;
            uint32_t bf[8][2];
            #pragma unroll
            for (int nf = 0; nf < 8; nf++) {
                bf[nf][0] = __float_as_uint(Vs[(k + tg    ) * FK_STRIDE + nf * 8 + g]);
                bf[nf][1] = __float_as_uint(Vs[(k + tg + 4) * FK_STRIDE + nf * 8 + g]);
            }
            uint32_t af[4];
            const int r = wm + g;
            af[0] = __float_as_uint(Ps[(r    ) * FQ_STRIDE + k + tg    ]);
            af[1] = __float_as_uint(Ps[(r + 8) * FQ_STRIDE + k + tg    ]);
            af[2] = __float_as_uint(Ps[(r    ) * FQ_STRIDE + k + tg + 4]);
            af[3] = __float_as_uint(Ps[(r + 8) * FQ_STRIDE + k + tg + 4]);
            #pragma unroll
            for (int nf = 0; nf < 8; nf++)
                mma_m16n8k8(ctx[nf], af, bf[nf]);
        }
    }

    // epilogue: reduce l across the 4 lanes sharing each row, normalize, write
    #pragma unroll
    for (int half = 0; half < 2; half++) {
        float l = lrow[half];
        l += __shfl_xor_sync(0xffffffffu, l, 1, 4);
        l += __shfl_xor_sync(0xffffffffu, l, 2, 4);
        const float inv = (l > 0.f) ? 1.f / l : 0.f;
        const int q = q0 + wm + g + half * 8;
        float* dst = &g_ctx[((size_t)b * SEQ + q) * DIM + h * HD];
        #pragma unroll
        for (int nf = 0; nf < 8; nf++) {
            float2 o;
            o.x = to_tf32(ctx[nf][half*2+0] * inv);
            o.y = to_tf32(ctx[nf][half*2+1] * inv);
            *(float2*)&dst[nf * 8 + 2 * tg] = o;
        }
    }
}

// ---------------------------------------------------------------------------
extern "C" void kernel_launch(void* const* d_in, const int* in_sizes, int n_in,
                              void* d_out, int out_size)
{
    (void)in_sizes; (void)n_in; (void)out_size;
    const float* query = (const float*)d_in[0];
    const float* key   = (const float*)d_in[1];
    const float* value = (const float*)d_in[2];
    const int*   mask  = (const int*)d_in[3];
    const float* Wq = (const float*)d_in[4];
    const float* bq = (const float*)d_in[5];
    const float* Wk = (const float*)d_in[6];
    const float* bk = (const float*)d_in[7];
    const float* Wv = (const float*)d_in[8];
    const float* bv = (const float*)d_in[9];
    const float* Wo = (const float*)d_in[10];
    const float* bo = (const float*)d_in[11];
    float* out = (float*)d_out;

    cudaFuncSetAttribute(qkv_mma_kernel, cudaFuncAttributeMaxDynamicSharedMemorySize, GEMM_SMEM);
    cudaFuncSetAttribute(out_mma_kernel, cudaFuncAttributeMaxDynamicSharedMemorySize, GEMM_SMEM);
    cudaFuncSetAttribute(flash_mma_kernel, cudaFuncAttributeMaxDynamicSharedMemorySize, FLASH_SMEM);

    prep_act_kernel<<<dim3(4096, 3), 256>>>(query, key, value);
    prep_w_kernel<<<dim3(1024, 4), 256>>>(Wq, Wk, Wv, Wo);

    dim3 gQKV(M_TOT / 256, NH / 2, 3);
    qkv_mma_kernel<<<gQKV, 512, GEMM_SMEM>>>(bq, bk, bv);

    dim3 gFA(SEQ / 128, BATCH * NH);
    flash_mma_kernel<<<gFA, 256, FLASH_SMEM>>>(mask);

    dim3 gOUT(M_TOT / 256, DIM / 128);
    out_mma_kernel<<<gOUT, 512, GEMM_SMEM>>>(bo, out);
}

// round 7
// speedup vs baseline: 9.6359x; 1.7154x over previous
#include <cuda_runtime.h>
#include <cuda_fp16.h>
#include <math.h>
#include <stdint.h>

#define BATCH 2
#define SEQ   2048
#define DIM   1024
#define NH    16
#define HD    64
#define M_TOT (BATCH*SEQ)           // 4096
#define SCALE_Q 0.18033688011112042f  // 0.125 * log2(e): scores in log2 domain

// ---- scratch (device globals; 16B-aligned for cp.async) ----
__device__ __align__(16) __half g_aq[(size_t)M_TOT*DIM];
__device__ __align__(16) __half g_ak[(size_t)M_TOT*DIM];
__device__ __align__(16) __half g_av[(size_t)M_TOT*DIM];
__device__ __align__(16) __half g_wq[(size_t)NH*HD*DIM];   // [h][e][k] (transposed)
__device__ __align__(16) __half g_wk[(size_t)NH*HD*DIM];
__device__ __align__(16) __half g_wv[(size_t)NH*HD*DIM];
__device__ __align__(16) __half g_wo[(size_t)DIM*DIM];     // [n][k] (transposed)
__device__ __align__(16) __half g_q [(size_t)BATCH*NH*SEQ*HD]; // [bh][s][e], pre-scaled
__device__ __align__(16) __half g_k [(size_t)BATCH*NH*SEQ*HD]; // [bh][s][e]
__device__ __align__(16) __half g_vT[(size_t)BATCH*NH*HD*SEQ]; // [bh][e][s]
__device__ __align__(16) __half g_ctx[(size_t)M_TOT*DIM];      // [b][s][h*HD+e]

// ---- helpers ----
__device__ __forceinline__ float ex2f(float x) {
    float y; asm("ex2.approx.f32 %0, %1;" : "=f"(y) : "f"(x)); return y;
}
__device__ __forceinline__ uint32_t smem_u32(const void* p) {
    return (uint32_t)__cvta_generic_to_shared(p);
}
#define CP_ASYNC16(dst, src) \
    asm volatile("cp.async.cg.shared.global [%0], [%1], 16;" :: "r"(dst), "l"(src))
#define CP_COMMIT() asm volatile("cp.async.commit_group;")
#define CP_WAIT0()  asm volatile("cp.async.wait_group 0;")

// D += A(16x16) * B(16x8), fp16 inputs, fp32 accum.
__device__ __forceinline__ void mma_f16(float* d, const uint32_t* a, const uint32_t* b) {
    asm volatile(
        "mma.sync.aligned.m16n8k16.row.col.f32.f16.f16.f32 "
        "{%0,%1,%2,%3}, {%4,%5,%6,%7}, {%8,%9}, {%0,%1,%2,%3};"
        : "+f"(d[0]), "+f"(d[1]), "+f"(d[2]), "+f"(d[3])
        : "r"(a[0]), "r"(a[1]), "r"(a[2]), "r"(a[3]), "r"(b[0]), "r"(b[1]));
}

// 64-half rows (32 words), 128B XOR swizzle. Returns half index of word start.
__device__ __forceinline__ int idx64(int r, int wc) {
    return r * 64 + ((wc ^ ((r & 7) << 2)) << 1);
}

// ---------------------------------------------------------------------------
// Prep
// ---------------------------------------------------------------------------
__global__ __launch_bounds__(256) void prep_act_kernel(
    const float* __restrict__ q, const float* __restrict__ k, const float* __restrict__ v)
{
    const int z = blockIdx.y;
    const float4* s = (const float4*)(z == 0 ? q : z == 1 ? k : v);
    __half* d = (z == 0 ? g_aq : z == 1 ? g_ak : g_av);
    const size_t i = (size_t)blockIdx.x * 256 + threadIdx.x;   // over 1M float4
    float4 x = s[i];
    __half2* dp = (__half2*)(d + i * 4);
    dp[0] = __floats2half2_rn(x.x, x.y);
    dp[1] = __floats2half2_rn(x.z, x.w);
}

// Transpose + convert: src fp32 [B][K][E] -> dst half [B][E][K]
__global__ __launch_bounds__(256) void prep_wT_kernel(
    const float* __restrict__ src, __half* __restrict__ dst, int K, int E)
{
    __shared__ float tile[32][33];
    const int b = blockIdx.z;
    const int k0 = blockIdx.x * 32, e0 = blockIdx.y * 32;
    const int tx = threadIdx.x & 31, ty = threadIdx.x >> 5;  // 32 x 8
    const float* s = src + (size_t)b * K * E;
    __half* d = dst + (size_t)b * K * E;
    #pragma unroll
    for (int j = 0; j < 32; j += 8)
        tile[ty + j][tx] = s[(size_t)(k0 + ty + j) * E + e0 + tx];
    __syncthreads();
    #pragma unroll
    for (int j = 0; j < 32; j += 8)
        d[(size_t)(e0 + ty + j) * K + k0 + tx] = __float2half_rn(tile[tx][ty + j]);
}

// ---------------------------------------------------------------------------
// GEMM: BM=256, BN=128, BK=64, 512 threads (16 warps: 8m x 2n), double-buffered.
// As [256][64h] swizzled; Bs [128 n][64 kh] swizzled (B pre-transposed in gmem).
// ---------------------------------------------------------------------------
#define GS_A (256*64)
#define GS_B (128*64)
#define G_STAGE_H (GS_A + GS_B)            // 24576 halves
#define GEMM_SMEM (2*G_STAGE_H*2)          // 98,304 B

__global__ __launch_bounds__(512) void qkv_mma_kernel(
    const float* __restrict__ bq, const float* __restrict__ bk, const float* __restrict__ bv)
{
    extern __shared__ __half smh[];
    const int which = blockIdx.z;
    const __half* A    = which == 0 ? g_aq : which == 1 ? g_ak : g_av;
    const __half* W    = which == 0 ? g_wq : which == 1 ? g_wk : g_wv;
    const float* bias  = which == 0 ? bq   : which == 1 ? bk   : bv;

    const int m0 = blockIdx.x * 256;
    const int hp = blockIdx.y;                 // head pair
    const int t = threadIdx.x;
    const int warp = t >> 5, lane = t & 31, g = lane >> 2, tg = lane & 3;
    const int wm = (warp >> 1) * 32, wn = (warp & 1) * 64;

    const __half* WbT = W + (size_t)(hp * 2) * HD * DIM;   // [128 rows n][1024 k]

    auto issue = [&](int k0, int st) {
        __half* As = smh + st * G_STAGE_H;
        __half* Bs = As + GS_A;
        #pragma unroll
        for (int j = 0; j < 4; j++) {
            const int lin = j * 512 + t;
            const int r = lin >> 3, c = lin & 7;
            CP_ASYNC16(smem_u32(&As[idx64(r, c * 4)]),
                       &A[(size_t)(m0 + r) * DIM + k0 + c * 8]);
        }
        #pragma unroll
        for (int j = 0; j < 2; j++) {
            const int lin = j * 512 + t;
            const int n = lin >> 3, c = lin & 7;
            CP_ASYNC16(smem_u32(&Bs[idx64(n, c * 4)]),
                       &WbT[(size_t)n * DIM + k0 + c * 8]);
        }
    };

    float acc[2][8][4];
    #pragma unroll
    for (int i = 0; i < 2; i++)
        #pragma unroll
        for (int j = 0; j < 8; j++)
            #pragma unroll
            for (int c = 0; c < 4; c++) acc[i][j][c] = 0.f;

    issue(0, 0); CP_COMMIT();
    for (int it = 0; it < DIM / 64; it++) {
        CP_WAIT0(); __syncthreads();
        if (it < DIM / 64 - 1) { issue((it + 1) * 64, (it + 1) & 1); CP_COMMIT(); }
        const __half* As = smh + (it & 1) * G_STAGE_H;
        const __half* Bs = As + GS_A;
        #pragma unroll
        for (int kk = 0; kk < 4; kk++) {
            uint32_t bf[8][2];
            #pragma unroll
            for (int nf = 0; nf < 8; nf++) {
                const int n = wn + nf * 8 + g;
                bf[nf][0] = *(const uint32_t*)&Bs[idx64(n, kk * 8 + tg)];
                bf[nf][1] = *(const uint32_t*)&Bs[idx64(n, kk * 8 + 4 + tg)];
            }
            uint32_t af[2][4];
            #pragma unroll
            for (int mf = 0; mf < 2; mf++) {
                const int r = wm + mf * 16 + g;
                af[mf][0] = *(const uint32_t*)&As[idx64(r,     kk * 8 + tg)];
                af[mf][1] = *(const uint32_t*)&As[idx64(r + 8, kk * 8 + tg)];
                af[mf][2] = *(const uint32_t*)&As[idx64(r,     kk * 8 + 4 + tg)];
                af[mf][3] = *(const uint32_t*)&As[idx64(r + 8, kk * 8 + 4 + tg)];
            }
            #pragma unroll
            for (int mf = 0; mf < 2; mf++)
                #pragma unroll
                for (int nf = 0; nf < 8; nf++)
                    mma_f16(acc[mf][nf], af[mf], bf[nf]);
        }
        __syncthreads();
    }

    const int h = hp * 2 + (wn >> 6);
    float2 bl[8];
    #pragma unroll
    for (int nf = 0; nf < 8; nf++)
        bl[nf] = *(const float2*)&bias[h * HD + nf * 8 + 2 * tg];

    #pragma unroll
    for (int mf = 0; mf < 2; mf++) {
        #pragma unroll
        for (int half_ = 0; half_ < 2; half_++) {
            const int m = m0 + wm + mf * 16 + g + half_ * 8;
            const int b = m >> 11, s = m & (SEQ - 1);
            const int bh = b * NH + h;
            if (which == 0) {
                __half* dst = g_q + ((size_t)bh * SEQ + s) * HD;
                #pragma unroll
                for (int nf = 0; nf < 8; nf++)
                    *(__half2*)&dst[nf * 8 + 2 * tg] = __floats2half2_rn(
                        (acc[mf][nf][half_*2+0] + bl[nf].x) * SCALE_Q,
                        (acc[mf][nf][half_*2+1] + bl[nf].y) * SCALE_Q);
            } else if (which == 1) {
                __half* dst = g_k + ((size_t)bh * SEQ + s) * HD;
                #pragma unroll
                for (int nf = 0; nf < 8; nf++)
                    *(__half2*)&dst[nf * 8 + 2 * tg] = __floats2half2_rn(
                        acc[mf][nf][half_*2+0] + bl[nf].x,
                        acc[mf][nf][half_*2+1] + bl[nf].y);
            } else {
                const size_t base = (size_t)bh * HD * SEQ;
                #pragma unroll
                for (int nf = 0; nf < 8; nf++) {
                    const int e = nf * 8 + 2 * tg;
                    g_vT[base + (size_t)(e    ) * SEQ + s] = __float2half_rn(acc[mf][nf][half_*2+0] + bl[nf].x);
                    g_vT[base + (size_t)(e + 1) * SEQ + s] = __float2half_rn(acc[mf][nf][half_*2+1] + bl[nf].y);
                }
            }
        }
    }
}

__global__ __launch_bounds__(512) void out_mma_kernel(
    const float* __restrict__ bo, float* __restrict__ out)
{
    extern __shared__ __half smh[];
    const int m0 = blockIdx.x * 256;
    const int n0 = blockIdx.y * 128;
    const int t = threadIdx.x;
    const int warp = t >> 5, lane = t & 31, g = lane >> 2, tg = lane & 3;
    const int wm = (warp >> 1) * 32, wn = (warp & 1) * 64;

    auto issue = [&](int k0, int st) {
        __half* As = smh + st * G_STAGE_H;
        __half* Bs = As + GS_A;
        #pragma unroll
        for (int j = 0; j < 4; j++) {
            const int lin = j * 512 + t;
            const int r = lin >> 3, c = lin & 7;
            CP_ASYNC16(smem_u32(&As[idx64(r, c * 4)]),
                       &g_ctx[(size_t)(m0 + r) * DIM + k0 + c * 8]);
        }
        #pragma unroll
        for (int j = 0; j < 2; j++) {
            const int lin = j * 512 + t;
            const int n = lin >> 3, c = lin & 7;
            CP_ASYNC16(smem_u32(&Bs[idx64(n, c * 4)]),
                       &g_wo[(size_t)(n0 + n) * DIM + k0 + c * 8]);
        }
    };

    float acc[2][8][4];
    #pragma unroll
    for (int i = 0; i < 2; i++)
        #pragma unroll
        for (int j = 0; j < 8; j++)
            #pragma unroll
            for (int c = 0; c < 4; c++) acc[i][j][c] = 0.f;

    issue(0, 0); CP_COMMIT();
    for (int it = 0; it < DIM / 64; it++) {
        CP_WAIT0(); __syncthreads();
        if (it < DIM / 64 - 1) { issue((it + 1) * 64, (it + 1) & 1); CP_COMMIT(); }
        const __half* As = smh + (it & 1) * G_STAGE_H;
        const __half* Bs = As + GS_A;
        #pragma unroll
        for (int kk = 0; kk < 4; kk++) {
            uint32_t bf[8][2];
            #pragma unroll
            for (int nf = 0; nf < 8; nf++) {
                const int n = wn + nf * 8 + g;
                bf[nf][0] = *(const uint32_t*)&Bs[idx64(n, kk * 8 + tg)];
                bf[nf][1] = *(const uint32_t*)&Bs[idx64(n, kk * 8 + 4 + tg)];
            }
            uint32_t af[2][4];
            #pragma unroll
            for (int mf = 0; mf < 2; mf++) {
                const int r = wm + mf * 16 + g;
                af[mf][0] = *(const uint32_t*)&As[idx64(r,     kk * 8 + tg)];
                af[mf][1] = *(const uint32_t*)&As[idx64(r + 8, kk * 8 + tg)];
                af[mf][2] = *(const uint32_t*)&As[idx64(r,     kk * 8 + 4 + tg)];
                af[mf][3] = *(const uint32_t*)&As[idx64(r + 8, kk * 8 + 4 + tg)];
            }
            #pragma unroll
            for (int mf = 0; mf < 2; mf++)
                #pragma unroll
                for (int nf = 0; nf < 8; nf++)
                    mma_f16(acc[mf][nf], af[mf], bf[nf]);
        }
        __syncthreads();
    }

    float2 bl[8];
    #pragma unroll
    for (int nf = 0; nf < 8; nf++)
        bl[nf] = *(const float2*)&bo[n0 + wn + nf * 8 + 2 * tg];

    #pragma unroll
    for (int mf = 0; mf < 2; mf++) {
        #pragma unroll
        for (int half_ = 0; half_ < 2; half_++) {
            const int m = m0 + wm + mf * 16 + g + half_ * 8;
            float* dst = out + (size_t)m * DIM + n0 + wn;
            #pragma unroll
            for (int nf = 0; nf < 8; nf++) {
                float2 o;
                o.x = acc[mf][nf][half_*2+0] + bl[nf].x;
                o.y = acc[mf][nf][half_*2+1] + bl[nf].y;
                *(float2*)&dst[nf * 8 + 2 * tg] = o;
            }
        }
    }
}

// ---------------------------------------------------------------------------
// Flash attention (fp16 operands): Q-tile 128, KV 64, 256 threads, 2 CTAs/SM.
// K consumed natural [kv][e]; V via g_vT [e][s]. Q fragments in registers.
// ---------------------------------------------------------------------------
#define FP_H   (128*64)     // Ps halves (16KB)
#define FKV_H  (2*64*64)    // K + Vt per stage (16KB)
#define FLASH_SMEM ((FP_H + 2*FKV_H) * 2)   // 49,152 B

__global__ __launch_bounds__(256, 2) void flash_mma_kernel(const int* __restrict__ mask)
{
    extern __shared__ __half smh[];
    __half* Ps = smh;               // [q 128][kv 64] swizzled
    __half* KV = smh + FP_H;

    const int bh = blockIdx.y;
    const int b = bh >> 4, h = bh & 15;
    const int q0 = blockIdx.x * 128;
    const int t = threadIdx.x;
    const int warp = t >> 5, lane = t & 31, g = lane >> 2, tg = lane & 3;
    const int wm = warp * 16;

    const __half* qp  = g_q  + ((size_t)bh * SEQ + q0) * HD;
    const __half* kp  = g_k  + (size_t)bh * SEQ * HD;
    const __half* vTp = g_vT + (size_t)bh * HD * SEQ;
    const int*    mp  = mask + (size_t)b * SEQ;

    // ---- Stage Q once through KV area; hoist fragments to registers ----
    {
        __half* Qs = KV;
        #pragma unroll
        for (int j = 0; j < 4; j++) {
            const int lin = j * 256 + t;
            const int r = lin >> 3, c = lin & 7;
            CP_ASYNC16(smem_u32(&Qs[idx64(r, c * 4)]),
                       &qp[(size_t)r * HD + c * 8]);
        }
        CP_COMMIT(); CP_WAIT0();
        __syncthreads();
    }
    uint32_t qf[4][4];
    {
        const __half* Qs = KV;
        const int r = wm + g;
        #pragma unroll
        for (int kk = 0; kk < 4; kk++) {
            qf[kk][0] = *(const uint32_t*)&Qs[idx64(r,     kk * 8 + tg)];
            qf[kk][1] = *(const uint32_t*)&Qs[idx64(r + 8, kk * 8 + tg)];
            qf[kk][2] = *(const uint32_t*)&Qs[idx64(r,     kk * 8 + 4 + tg)];
            qf[kk][3] = *(const uint32_t*)&Qs[idx64(r + 8, kk * 8 + 4 + tg)];
        }
        __syncthreads();
    }

    auto issue_kv = [&](int kv0, int st) {
        __half* Ks = KV + st * FKV_H;
        __half* Vt = Ks + 64 * 64;
        #pragma unroll
        for (int j = 0; j < 2; j++) {
            const int lin = j * 256 + t;
            const int r = lin >> 3, c = lin & 7;
            CP_ASYNC16(smem_u32(&Ks[idx64(r, c * 4)]),
                       &kp[(size_t)(kv0 + r) * HD + c * 8]);
        }
        #pragma unroll
        for (int j = 0; j < 2; j++) {
            const int lin = j * 256 + t;
            const int r = lin >> 3, c = lin & 7;
            CP_ASYNC16(smem_u32(&Vt[idx64(r, c * 4)]),
                       &vTp[(size_t)r * SEQ + kv0 + c * 8]);
        }
    };

    issue_kv(0, 0); CP_COMMIT();

    float ctx[8][4];
    #pragma unroll
    for (int j = 0; j < 8; j++)
        #pragma unroll
        for (int c = 0; c < 4; c++) ctx[j][c] = 0.f;
    float lrow[2] = {0.f, 0.f};

    for (int it = 0; it < SEQ / 64; it++) {
        CP_WAIT0(); __syncthreads();
        if (it < SEQ / 64 - 1) { issue_kv((it + 1) * 64, (it + 1) & 1); CP_COMMIT(); }
        const __half* Ks = KV + (it & 1) * FKV_H;
        const __half* Vt = Ks + 64 * 64;

        // --- S = Q . K^T (log2 domain); B = K natural [kv][e] ---
        float sacc[8][4];
        #pragma unroll
        for (int j = 0; j < 8; j++)
            #pragma unroll
            for (int c = 0; c < 4; c++) sacc[j][c] = 0.f;

        #pragma unroll
        for (int kk = 0; kk < 4; kk++) {
            uint32_t bf[8][2];
            #pragma unroll
            for (int nf = 0; nf < 8; nf++) {
                const int n = nf * 8 + g;   // kv row
                bf[nf][0] = *(const uint32_t*)&Ks[idx64(n, kk * 8 + tg)];
                bf[nf][1] = *(const uint32_t*)&Ks[idx64(n, kk * 8 + 4 + tg)];
            }
            #pragma unroll
            for (int nf = 0; nf < 8; nf++)
                mma_f16(sacc[nf], qf[kk], bf[nf]);
        }

        // --- mask -> exp2 -> P (half2) + l accumulation ---
        const int kvb = it * 64;
        #pragma unroll
        for (int nf = 0; nf < 8; nf++) {
            const int2 mv = *(const int2*)&mp[kvb + nf * 8 + 2 * tg];
            if (!mv.x) { sacc[nf][0] = -1e9f; sacc[nf][2] = -1e9f; }
            if (!mv.y) { sacc[nf][1] = -1e9f; sacc[nf][3] = -1e9f; }
            float p0 = ex2f(sacc[nf][0]);
            float p1 = ex2f(sacc[nf][1]);
            float p2 = ex2f(sacc[nf][2]);
            float p3 = ex2f(sacc[nf][3]);
            lrow[0] += p0 + p1;
            lrow[1] += p2 + p3;
            *(__half2*)&Ps[idx64(wm + g,     nf * 4 + tg)] = __floats2half2_rn(p0, p1);
            *(__half2*)&Ps[idx64(wm + g + 8, nf * 4 + tg)] = __floats2half2_rn(p2, p3);
        }
        __syncwarp();

        // --- ctx += P . V; B = V^T [d][kv] ---
        #pragma unroll
        for (int kk = 0; kk < 4; kk++) {
            uint32_t af[4];
            const int r = wm + g;
            af[0] = *(const uint32_t*)&Ps[idx64(r,     kk * 8 + tg)];
            af[1] = *(const uint32_t*)&Ps[idx64(r + 8, kk * 8 + tg)];
            af[2] = *(const uint32_t*)&Ps[idx64(r,     kk * 8 + 4 + tg)];
            af[3] = *(const uint32_t*)&Ps[idx64(r + 8, kk * 8 + 4 + tg)];
            uint32_t bf[8][2];
            #pragma unroll
            for (int nf = 0; nf < 8; nf++) {
                const int n = nf * 8 + g;   // d row
                bf[nf][0] = *(const uint32_t*)&Vt[idx64(n, kk * 8 + tg)];
                bf[nf][1] = *(const uint32_t*)&Vt[idx64(n, kk * 8 + 4 + tg)];
            }
            #pragma unroll
            for (int nf = 0; nf < 8; nf++)
                mma_f16(ctx[nf], af, bf[nf]);
        }
    }

    // epilogue: reduce l over 4 lanes per row, normalize, write half ctx
    #pragma unroll
    for (int half_ = 0; half_ < 2; half_++) {
        float l = lrow[half_];
        l += __shfl_xor_sync(0xffffffffu, l, 1, 4);
        l += __shfl_xor_sync(0xffffffffu, l, 2, 4);
        const float inv = (l > 0.f) ? 1.f / l : 0.f;
        const int q = q0 + wm + g + half_ * 8;
        __half* dst = &g_ctx[((size_t)b * SEQ + q) * DIM + h * HD];
        #pragma unroll
        for (int nf = 0; nf < 8; nf++)
            *(__half2*)&dst[nf * 8 + 2 * tg] = __floats2half2_rn(
                ctx[nf][half_*2+0] * inv, ctx[nf][half_*2+1] * inv);
    }
}

// ---------------------------------------------------------------------------
extern "C" void kernel_launch(void* const* d_in, const int* in_sizes, int n_in,
                              void* d_out, int out_size)
{
    (void)in_sizes; (void)n_in; (void)out_size;
    const float* query = (const float*)d_in[0];
    const float* key   = (const float*)d_in[1];
    const float* value = (const float*)d_in[2];
    const int*   mask  = (const int*)d_in[3];
    const float* Wq = (const float*)d_in[4];
    const float* bq = (const float*)d_in[5];
    const float* Wk = (const float*)d_in[6];
    const float* bk = (const float*)d_in[7];
    const float* Wv = (const float*)d_in[8];
    const float* bv = (const float*)d_in[9];
    const float* Wo = (const float*)d_in[10];
    const float* bo = (const float*)d_in[11];
    float* out = (float*)d_out;

    cudaFuncSetAttribute(qkv_mma_kernel, cudaFuncAttributeMaxDynamicSharedMemorySize, GEMM_SMEM);
    cudaFuncSetAttribute(out_mma_kernel, cudaFuncAttributeMaxDynamicSharedMemorySize, GEMM_SMEM);
    cudaFuncSetAttribute(flash_mma_kernel, cudaFuncAttributeMaxDynamicSharedMemorySize, FLASH_SMEM);

    prep_act_kernel<<<dim3(4096, 3), 256>>>(query, key, value);

    __half *d_wq, *d_wk, *d_wv, *d_wo;
    cudaGetSymbolAddress((void**)&d_wq, g_wq);
    cudaGetSymbolAddress((void**)&d_wk, g_wk);
    cudaGetSymbolAddress((void**)&d_wv, g_wv);
    cudaGetSymbolAddress((void**)&d_wo, g_wo);
    prep_wT_kernel<<<dim3(32, 2, 16), 256>>>(Wq, d_wq, DIM, HD);
    prep_wT_kernel<<<dim3(32, 2, 16), 256>>>(Wk, d_wk, DIM, HD);
    prep_wT_kernel<<<dim3(32, 2, 16), 256>>>(Wv, d_wv, DIM, HD);
    prep_wT_kernel<<<dim3(32, 32, 1), 256>>>(Wo, d_wo, DIM, DIM);

    dim3 gQKV(M_TOT / 256, NH / 2, 3);
    qkv_mma_kernel<<<gQKV, 512, GEMM_SMEM>>>(bq, bk, bv);

    dim3 gFA(SEQ / 128, BATCH * NH);
    flash_mma_kernel<<<gFA, 256, FLASH_SMEM>>>(mask);

    dim3 gOUT(M_TOT / 256, DIM / 128);
    out_mma_kernel<<<gOUT, 512, GEMM_SMEM>>>(bo, out);
}

// round 8
// speedup vs baseline: 10.4358x; 1.0830x over previous
#include <cuda_runtime.h>
#include <cuda_fp16.h>
#include <math.h>
#include <stdint.h>

#define BATCH 2
#define SEQ   2048
#define DIM   1024
#define NH    16
#define HD    64
#define M_TOT (BATCH*SEQ)           // 4096
#define SCALE_Q 0.18033688011112042f  // 0.125 * log2(e): scores in log2 domain

// ---- scratch (device globals; 16B-aligned for cp.async) ----
__device__ __align__(16) __half g_aq[(size_t)M_TOT*DIM];
__device__ __align__(16) __half g_ak[(size_t)M_TOT*DIM];
__device__ __align__(16) __half g_av[(size_t)M_TOT*DIM];
__device__ __align__(16) __half g_wq[(size_t)NH*HD*DIM];   // [h][e][k] (transposed)
__device__ __align__(16) __half g_wk[(size_t)NH*HD*DIM];
__device__ __align__(16) __half g_wv[(size_t)NH*HD*DIM];
__device__ __align__(16) __half g_wo[(size_t)DIM*DIM];     // [n][k] (transposed)
__device__ __align__(16) __half g_q [(size_t)BATCH*NH*SEQ*HD]; // [bh][s][e], pre-scaled
__device__ __align__(16) __half g_k [(size_t)BATCH*NH*SEQ*HD]; // [bh][s][e]
__device__ __align__(16) __half g_vT[(size_t)BATCH*NH*HD*SEQ]; // [bh][e][s]
__device__ __align__(16) __half g_ctx[(size_t)M_TOT*DIM];      // [b][s][h*HD+e]

// ---- helpers ----
__device__ __forceinline__ float ex2f(float x) {
    float y; asm("ex2.approx.f32 %0, %1;" : "=f"(y) : "f"(x)); return y;
}
__device__ __forceinline__ uint32_t smem_u32(const void* p) {
    return (uint32_t)__cvta_generic_to_shared(p);
}
__device__ __forceinline__ uint32_t packh2(float a, float b) {
    __half2 h = __floats2half2_rn(a, b);
    return *(uint32_t*)&h;
}
#define CP_ASYNC16(dst, src) \
    asm volatile("cp.async.cg.shared.global [%0], [%1], 16;" :: "r"(dst), "l"(src))
#define CP_COMMIT() asm volatile("cp.async.commit_group;")
#define CP_WAIT0()  asm volatile("cp.async.wait_group 0;")

// D += A(16x16) * B(16x8), fp16 inputs, fp32 accum.
__device__ __forceinline__ void mma_f16(float* d, const uint32_t* a, const uint32_t* b) {
    asm volatile(
        "mma.sync.aligned.m16n8k16.row.col.f32.f16.f16.f32 "
        "{%0,%1,%2,%3}, {%4,%5,%6,%7}, {%8,%9}, {%0,%1,%2,%3};"
        : "+f"(d[0]), "+f"(d[1]), "+f"(d[2]), "+f"(d[3])
        : "r"(a[0]), "r"(a[1]), "r"(a[2]), "r"(a[3]), "r"(b[0]), "r"(b[1]));
}

// 64-half rows (32 words), 128B XOR swizzle. Returns half index of word start.
__device__ __forceinline__ int idx64(int r, int wc) {
    return r * 64 + ((wc ^ ((r & 7) << 2)) << 1);
}

// ---------------------------------------------------------------------------
// Prep
// ---------------------------------------------------------------------------
__global__ __launch_bounds__(256) void prep_act_kernel(
    const float* __restrict__ q, const float* __restrict__ k, const float* __restrict__ v)
{
    const int z = blockIdx.y;
    const float4* s = (const float4*)(z == 0 ? q : z == 1 ? k : v);
    __half* d = (z == 0 ? g_aq : z == 1 ? g_ak : g_av);
    const size_t i = (size_t)blockIdx.x * 256 + threadIdx.x;
    float4 x = s[i];
    __half2* dp = (__half2*)(d + i * 4);
    dp[0] = __floats2half2_rn(x.x, x.y);
    dp[1] = __floats2half2_rn(x.z, x.w);
}

// Transpose + convert: src fp32 [B][K][E] -> dst half [B][E][K]
__global__ __launch_bounds__(256) void prep_wT_kernel(
    const float* __restrict__ src, __half* __restrict__ dst, int K, int E)
{
    __shared__ float tile[32][33];
    const int b = blockIdx.z;
    const int k0 = blockIdx.x * 32, e0 = blockIdx.y * 32;
    const int tx = threadIdx.x & 31, ty = threadIdx.x >> 5;  // 32 x 8
    const float* s = src + (size_t)b * K * E;
    __half* d = dst + (size_t)b * K * E;
    #pragma unroll
    for (int j = 0; j < 32; j += 8)
        tile[ty + j][tx] = s[(size_t)(k0 + ty + j) * E + e0 + tx];
    __syncthreads();
    #pragma unroll
    for (int j = 0; j < 32; j += 8)
        d[(size_t)(e0 + ty + j) * K + k0 + tx] = __float2half_rn(tile[tx][ty + j]);
}

// ---------------------------------------------------------------------------
// GEMM: BM=256, BN=128, BK=64, 512 threads (16 warps: 8m x 2n), double-buffered.
// ---------------------------------------------------------------------------
#define GS_A (256*64)
#define GS_B (128*64)
#define G_STAGE_H (GS_A + GS_B)            // 24576 halves
#define GEMM_SMEM (2*G_STAGE_H*2)          // 98,304 B

__global__ __launch_bounds__(512) void qkv_mma_kernel(
    const float* __restrict__ bq, const float* __restrict__ bk, const float* __restrict__ bv)
{
    extern __shared__ __half smh[];
    const int which = blockIdx.z;
    const __half* A    = which == 0 ? g_aq : which == 1 ? g_ak : g_av;
    const __half* W    = which == 0 ? g_wq : which == 1 ? g_wk : g_wv;
    const float* bias  = which == 0 ? bq   : which == 1 ? bk   : bv;

    const int m0 = blockIdx.x * 256;
    const int hp = blockIdx.y;
    const int t = threadIdx.x;
    const int warp = t >> 5, lane = t & 31, g = lane >> 2, tg = lane & 3;
    const int wm = (warp >> 1) * 32, wn = (warp & 1) * 64;

    const __half* WbT = W + (size_t)(hp * 2) * HD * DIM;

    auto issue = [&](int k0, int st) {
        __half* As = smh + st * G_STAGE_H;
        __half* Bs = As + GS_A;
        #pragma unroll
        for (int j = 0; j < 4; j++) {
            const int lin = j * 512 + t;
            const int r = lin >> 3, c = lin & 7;
            CP_ASYNC16(smem_u32(&As[idx64(r, c * 4)]),
                       &A[(size_t)(m0 + r) * DIM + k0 + c * 8]);
        }
        #pragma unroll
        for (int j = 0; j < 2; j++) {
            const int lin = j * 512 + t;
            const int n = lin >> 3, c = lin & 7;
            CP_ASYNC16(smem_u32(&Bs[idx64(n, c * 4)]),
                       &WbT[(size_t)n * DIM + k0 + c * 8]);
        }
    };

    float acc[2][8][4];
    #pragma unroll
    for (int i = 0; i < 2; i++)
        #pragma unroll
        for (int j = 0; j < 8; j++)
            #pragma unroll
            for (int c = 0; c < 4; c++) acc[i][j][c] = 0.f;

    issue(0, 0); CP_COMMIT();
    for (int it = 0; it < DIM / 64; it++) {
        CP_WAIT0(); __syncthreads();
        if (it < DIM / 64 - 1) { issue((it + 1) * 64, (it + 1) & 1); CP_COMMIT(); }
        const __half* As = smh + (it & 1) * G_STAGE_H;
        const __half* Bs = As + GS_A;
        #pragma unroll
        for (int kk = 0; kk < 4; kk++) {
            uint32_t bf[8][2];
            #pragma unroll
            for (int nf = 0; nf < 8; nf++) {
                const int n = wn + nf * 8 + g;
                bf[nf][0] = *(const uint32_t*)&Bs[idx64(n, kk * 8 + tg)];
                bf[nf][1] = *(const uint32_t*)&Bs[idx64(n, kk * 8 + 4 + tg)];
            }
            uint32_t af[2][4];
            #pragma unroll
            for (int mf = 0; mf < 2; mf++) {
                const int r = wm + mf * 16 + g;
                af[mf][0] = *(const uint32_t*)&As[idx64(r,     kk * 8 + tg)];
                af[mf][1] = *(const uint32_t*)&As[idx64(r + 8, kk * 8 + tg)];
                af[mf][2] = *(const uint32_t*)&As[idx64(r,     kk * 8 + 4 + tg)];
                af[mf][3] = *(const uint32_t*)&As[idx64(r + 8, kk * 8 + 4 + tg)];
            }
            #pragma unroll
            for (int mf = 0; mf < 2; mf++)
                #pragma unroll
                for (int nf = 0; nf < 8; nf++)
                    mma_f16(acc[mf][nf], af[mf], bf[nf]);
        }
        __syncthreads();
    }

    const int h = hp * 2 + (wn >> 6);
    float2 bl[8];
    #pragma unroll
    for (int nf = 0; nf < 8; nf++)
        bl[nf] = *(const float2*)&bias[h * HD + nf * 8 + 2 * tg];

    #pragma unroll
    for (int mf = 0; mf < 2; mf++) {
        #pragma unroll
        for (int half_ = 0; half_ < 2; half_++) {
            const int m = m0 + wm + mf * 16 + g + half_ * 8;
            const int b = m >> 11, s = m & (SEQ - 1);
            const int bh = b * NH + h;
            if (which == 0) {
                __half* dst = g_q + ((size_t)bh * SEQ + s) * HD;
                #pragma unroll
                for (int nf = 0; nf < 8; nf++)
                    *(__half2*)&dst[nf * 8 + 2 * tg] = __floats2half2_rn(
                        (acc[mf][nf][half_*2+0] + bl[nf].x) * SCALE_Q,
                        (acc[mf][nf][half_*2+1] + bl[nf].y) * SCALE_Q);
            } else if (which == 1) {
                __half* dst = g_k + ((size_t)bh * SEQ + s) * HD;
                #pragma unroll
                for (int nf = 0; nf < 8; nf++)
                    *(__half2*)&dst[nf * 8 + 2 * tg] = __floats2half2_rn(
                        acc[mf][nf][half_*2+0] + bl[nf].x,
                        acc[mf][nf][half_*2+1] + bl[nf].y);
            } else {
                const size_t base = (size_t)bh * HD * SEQ;
                #pragma unroll
                for (int nf = 0; nf < 8; nf++) {
                    const int e = nf * 8 + 2 * tg;
                    g_vT[base + (size_t)(e    ) * SEQ + s] = __float2half_rn(acc[mf][nf][half_*2+0] + bl[nf].x);
                    g_vT[base + (size_t)(e + 1) * SEQ + s] = __float2half_rn(acc[mf][nf][half_*2+1] + bl[nf].y);
                }
            }
        }
    }
}

__global__ __launch_bounds__(512) void out_mma_kernel(
    const float* __restrict__ bo, float* __restrict__ out)
{
    extern __shared__ __half smh[];
    const int m0 = blockIdx.x * 256;
    const int n0 = blockIdx.y * 128;
    const int t = threadIdx.x;
    const int warp = t >> 5, lane = t & 31, g = lane >> 2, tg = lane & 3;
    const int wm = (warp >> 1) * 32, wn = (warp & 1) * 64;

    auto issue = [&](int k0, int st) {
        __half* As = smh + st * G_STAGE_H;
        __half* Bs = As + GS_A;
        #pragma unroll
        for (int j = 0; j < 4; j++) {
            const int lin = j * 512 + t;
            const int r = lin >> 3, c = lin & 7;
            CP_ASYNC16(smem_u32(&As[idx64(r, c * 4)]),
                       &g_ctx[(size_t)(m0 + r) * DIM + k0 + c * 8]);
        }
        #pragma unroll
        for (int j = 0; j < 2; j++) {
            const int lin = j * 512 + t;
            const int n = lin >> 3, c = lin & 7;
            CP_ASYNC16(smem_u32(&Bs[idx64(n, c * 4)]),
                       &g_wo[(size_t)(n0 + n) * DIM + k0 + c * 8]);
        }
    };

    float acc[2][8][4];
    #pragma unroll
    for (int i = 0; i < 2; i++)
        #pragma unroll
        for (int j = 0; j < 8; j++)
            #pragma unroll
            for (int c = 0; c < 4; c++) acc[i][j][c] = 0.f;

    issue(0, 0); CP_COMMIT();
    for (int it = 0; it < DIM / 64; it++) {
        CP_WAIT0(); __syncthreads();
        if (it < DIM / 64 - 1) { issue((it + 1) * 64, (it + 1) & 1); CP_COMMIT(); }
        const __half* As = smh + (it & 1) * G_STAGE_H;
        const __half* Bs = As + GS_A;
        #pragma unroll
        for (int kk = 0; kk < 4; kk++) {
            uint32_t bf[8][2];
            #pragma unroll
            for (int nf = 0; nf < 8; nf++) {
                const int n = wn + nf * 8 + g;
                bf[nf][0] = *(const uint32_t*)&Bs[idx64(n, kk * 8 + tg)];
                bf[nf][1] = *(const uint32_t*)&Bs[idx64(n, kk * 8 + 4 + tg)];
            }
            uint32_t af[2][4];
            #pragma unroll
            for (int mf = 0; mf < 2; mf++) {
                const int r = wm + mf * 16 + g;
                af[mf][0] = *(const uint32_t*)&As[idx64(r,     kk * 8 + tg)];
                af[mf][1] = *(const uint32_t*)&As[idx64(r + 8, kk * 8 + tg)];
                af[mf][2] = *(const uint32_t*)&As[idx64(r,     kk * 8 + 4 + tg)];
                af[mf][3] = *(const uint32_t*)&As[idx64(r + 8, kk * 8 + 4 + tg)];
            }
            #pragma unroll
            for (int mf = 0; mf < 2; mf++)
                #pragma unroll
                for (int nf = 0; nf < 8; nf++)
                    mma_f16(acc[mf][nf], af[mf], bf[nf]);
        }
        __syncthreads();
    }

    float2 bl[8];
    #pragma unroll
    for (int nf = 0; nf < 8; nf++)
        bl[nf] = *(const float2*)&bo[n0 + wn + nf * 8 + 2 * tg];

    #pragma unroll
    for (int mf = 0; mf < 2; mf++) {
        #pragma unroll
        for (int half_ = 0; half_ < 2; half_++) {
            const int m = m0 + wm + mf * 16 + g + half_ * 8;
            float* dst = out + (size_t)m * DIM + n0 + wn;
            #pragma unroll
            for (int nf = 0; nf < 8; nf++) {
                float2 o;
                o.x = acc[mf][nf][half_*2+0] + bl[nf].x;
                o.y = acc[mf][nf][half_*2+1] + bl[nf].y;
                *(float2*)&dst[nf * 8 + 2 * tg] = o;
            }
        }
    }
}

// ---------------------------------------------------------------------------
// Flash attention: Q-tile 128, KV 64, 256 threads, 2 CTAs/SM.
// P kept in REGISTERS: the S-accumulator fragment of m16n8k16 has exactly the
// A-fragment layout of the following P.V mma (FA2 trick) -> no P smem buffer.
// K consumed natural [kv][e]; V via g_vT [e][s]. Q fragments in registers.
// ---------------------------------------------------------------------------
#define FKV_H  (2*64*64)                    // K + Vt per stage (16KB)
#define FLASH_SMEM (2*FKV_H*2)              // 32,768 B

__global__ __launch_bounds__(256, 2) void flash_mma_kernel(const int* __restrict__ mask)
{
    extern __shared__ __half smh[];
    __half* KV = smh;               // 2 stages x (Ks [64][64] + Vt [64][64])

    const int bh = blockIdx.y;
    const int b = bh >> 4, h = bh & 15;
    const int q0 = blockIdx.x * 128;
    const int t = threadIdx.x;
    const int warp = t >> 5, lane = t & 31, g = lane >> 2, tg = lane & 3;
    const int wm = warp * 16;

    const __half* qp  = g_q  + ((size_t)bh * SEQ + q0) * HD;
    const __half* kp  = g_k  + (size_t)bh * SEQ * HD;
    const __half* vTp = g_vT + (size_t)bh * HD * SEQ;
    const int*    mp  = mask + (size_t)b * SEQ;

    // ---- Stage Q once through KV stage 0; hoist fragments to registers ----
    {
        __half* Qs = KV;
        #pragma unroll
        for (int j = 0; j < 4; j++) {
            const int lin = j * 256 + t;
            const int r = lin >> 3, c = lin & 7;
            CP_ASYNC16(smem_u32(&Qs[idx64(r, c * 4)]),
                       &qp[(size_t)r * HD + c * 8]);
        }
        CP_COMMIT(); CP_WAIT0();
        __syncthreads();
    }
    uint32_t qf[4][4];
    {
        const __half* Qs = KV;
        const int r = wm + g;
        #pragma unroll
        for (int kk = 0; kk < 4; kk++) {
            qf[kk][0] = *(const uint32_t*)&Qs[idx64(r,     kk * 8 + tg)];
            qf[kk][1] = *(const uint32_t*)&Qs[idx64(r + 8, kk * 8 + tg)];
            qf[kk][2] = *(const uint32_t*)&Qs[idx64(r,     kk * 8 + 4 + tg)];
            qf[kk][3] = *(const uint32_t*)&Qs[idx64(r + 8, kk * 8 + 4 + tg)];
        }
        __syncthreads();   // all reads done before KV prologue overwrites
    }

    auto issue_kv = [&](int kv0, int st) {
        __half* Ks = KV + st * FKV_H;
        __half* Vt = Ks + 64 * 64;
        #pragma unroll
        for (int j = 0; j < 2; j++) {
            const int lin = j * 256 + t;
            const int r = lin >> 3, c = lin & 7;
            CP_ASYNC16(smem_u32(&Ks[idx64(r, c * 4)]),
                       &kp[(size_t)(kv0 + r) * HD + c * 8]);
        }
        #pragma unroll
        for (int j = 0; j < 2; j++) {
            const int lin = j * 256 + t;
            const int r = lin >> 3, c = lin & 7;
            CP_ASYNC16(smem_u32(&Vt[idx64(r, c * 4)]),
                       &vTp[(size_t)r * SEQ + kv0 + c * 8]);
        }
    };

    issue_kv(0, 0); CP_COMMIT();

    float ctx[8][4];
    #pragma unroll
    for (int j = 0; j < 8; j++)
        #pragma unroll
        for (int c = 0; c < 4; c++) ctx[j][c] = 0.f;
    float lrow[2] = {0.f, 0.f};

    for (int it = 0; it < SEQ / 64; it++) {
        CP_WAIT0(); __syncthreads();
        if (it < SEQ / 64 - 1) { issue_kv((it + 1) * 64, (it + 1) & 1); CP_COMMIT(); }
        const __half* Ks = KV + (it & 1) * FKV_H;
        const __half* Vt = Ks + 64 * 64;

        // --- S = Q . K^T (log2 domain); B = K natural [kv][e] ---
        float sacc[8][4];
        #pragma unroll
        for (int j = 0; j < 8; j++)
            #pragma unroll
            for (int c = 0; c < 4; c++) sacc[j][c] = 0.f;

        #pragma unroll
        for (int kk = 0; kk < 4; kk++) {
            uint32_t bf[8][2];
            #pragma unroll
            for (int nf = 0; nf < 8; nf++) {
                const int n = nf * 8 + g;
                bf[nf][0] = *(const uint32_t*)&Ks[idx64(n, kk * 8 + tg)];
                bf[nf][1] = *(const uint32_t*)&Ks[idx64(n, kk * 8 + 4 + tg)];
            }
            #pragma unroll
            for (int nf = 0; nf < 8; nf++)
                mma_f16(sacc[nf], qf[kk], bf[nf]);
        }

        // --- mask -> exp2 -> pack P directly into PV A-fragments ---
        const int kvb = it * 64;
        uint32_t pf[4][4];
        #pragma unroll
        for (int nf = 0; nf < 8; nf++) {
            const int2 mv = *(const int2*)&mp[kvb + nf * 8 + 2 * tg];
            if (!mv.x) { sacc[nf][0] = -1e9f; sacc[nf][2] = -1e9f; }
            if (!mv.y) { sacc[nf][1] = -1e9f; sacc[nf][3] = -1e9f; }
            float p0 = ex2f(sacc[nf][0]);
            float p1 = ex2f(sacc[nf][1]);
            float p2 = ex2f(sacc[nf][2]);
            float p3 = ex2f(sacc[nf][3]);
            lrow[0] += p0 + p1;
            lrow[1] += p2 + p3;
            // S-frag (rows g/g+8, cols nf*8+2tg,+1) == PV A-frag slots:
            // nf = 2*kk   -> af[kk][0] (row g), af[kk][1] (row g+8)   [k = 16kk+2tg]
            // nf = 2*kk+1 -> af[kk][2],        af[kk][3]              [k = 16kk+8+2tg]
            pf[nf >> 1][(nf & 1) * 2 + 0] = packh2(p0, p1);
            pf[nf >> 1][(nf & 1) * 2 + 1] = packh2(p2, p3);
        }

        // --- ctx += P . V; A from registers, B = V^T [d][kv] ---
        #pragma unroll
        for (int kk = 0; kk < 4; kk++) {
            uint32_t bf[8][2];
            #pragma unroll
            for (int nf = 0; nf < 8; nf++) {
                const int n = nf * 8 + g;
                bf[nf][0] = *(const uint32_t*)&Vt[idx64(n, kk * 8 + tg)];
                bf[nf][1] = *(const uint32_t*)&Vt[idx64(n, kk * 8 + 4 + tg)];
            }
            #pragma unroll
            for (int nf = 0; nf < 8; nf++)
                mma_f16(ctx[nf], pf[kk], bf[nf]);
        }
    }

    // epilogue: reduce l over 4 lanes per row, normalize, write half ctx
    #pragma unroll
    for (int half_ = 0; half_ < 2; half_++) {
        float l = lrow[half_];
        l += __shfl_xor_sync(0xffffffffu, l, 1, 4);
        l += __shfl_xor_sync(0xffffffffu, l, 2, 4);
        const float inv = (l > 0.f) ? 1.f / l : 0.f;
        const int q = q0 + wm + g + half_ * 8;
        __half* dst = &g_ctx[((size_t)b * SEQ + q) * DIM + h * HD];
        #pragma unroll
        for (int nf = 0; nf < 8; nf++)
            *(__half2*)&dst[nf * 8 + 2 * tg] = __floats2half2_rn(
                ctx[nf][half_*2+0] * inv, ctx[nf][half_*2+1] * inv);
    }
}

// ---------------------------------------------------------------------------
extern "C" void kernel_launch(void* const* d_in, const int* in_sizes, int n_in,
                              void* d_out, int out_size)
{
    (void)in_sizes; (void)n_in; (void)out_size;
    const float* query = (const float*)d_in[0];
    const float* key   = (const float*)d_in[1];
    const float* value = (const float*)d_in[2];
    const int*   mask  = (const int*)d_in[3];
    const float* Wq = (const float*)d_in[4];
    const float* bq = (const float*)d_in[5];
    const float* Wk = (const float*)d_in[6];
    const float* bk = (const float*)d_in[7];
    const float* Wv = (const float*)d_in[8];
    const float* bv = (const float*)d_in[9];
    const float* Wo = (const float*)d_in[10];
    const float* bo = (const float*)d_in[11];
    float* out = (float*)d_out;

    cudaFuncSetAttribute(qkv_mma_kernel, cudaFuncAttributeMaxDynamicSharedMemorySize, GEMM_SMEM);
    cudaFuncSetAttribute(out_mma_kernel, cudaFuncAttributeMaxDynamicSharedMemorySize, GEMM_SMEM);
    cudaFuncSetAttribute(flash_mma_kernel, cudaFuncAttributeMaxDynamicSharedMemorySize, FLASH_SMEM);

    prep_act_kernel<<<dim3(4096, 3), 256>>>(query, key, value);

    __half *d_wq, *d_wk, *d_wv, *d_wo;
    cudaGetSymbolAddress((void**)&d_wq, g_wq);
    cudaGetSymbolAddress((void**)&d_wk, g_wk);
    cudaGetSymbolAddress((void**)&d_wv, g_wv);
    cudaGetSymbolAddress((void**)&d_wo, g_wo);
    prep_wT_kernel<<<dim3(32, 2, 16), 256>>>(Wq, d_wq, DIM, HD);
    prep_wT_kernel<<<dim3(32, 2, 16), 256>>>(Wk, d_wk, DIM, HD);
    prep_wT_kernel<<<dim3(32, 2, 16), 256>>>(Wv, d_wv, DIM, HD);
    prep_wT_kernel<<<dim3(32, 32, 1), 256>>>(Wo, d_wo, DIM, DIM);

    dim3 gQKV(M_TOT / 256, NH / 2, 3);
    qkv_mma_kernel<<<gQKV, 512, GEMM_SMEM>>>(bq, bk, bv);

    dim3 gFA(SEQ / 128, BATCH * NH);
    flash_mma_kernel<<<gFA, 256, FLASH_SMEM>>>(mask);

    dim3 gOUT(M_TOT / 256, DIM / 128);
    out_mma_kernel<<<gOUT, 512, GEMM_SMEM>>>(bo, out);
}